// round 8
// baseline (speedup 1.0000x reference)
#include <cuda_runtime.h>
#include <cuda_fp16.h>
#include <mma.h>
using namespace nvcuda;

#define NB 512
#define NT 64
#define ND 128
#define NH 128

__device__ float  g_alpha[128];
__device__ __align__(16) float  g_Xa[NB*NT*ND];
__device__ __align__(16) __half g_Xh[NB*NT*ND];
__device__ __align__(16) __half g_wihh[512*128];
__device__ __align__(16) __half g_whhT[128*512];   // [k][g]
__device__ __align__(16) __half g_W1hc[256*128];   // [j][n]
__device__ __align__(16) __half g_W1x[64*128];
__device__ __align__(16) float  g_bsum[512];
__device__ __align__(16) float  g_gih[(size_t)NB*NT*512];
__device__ __align__(16) __half g_XpW[(size_t)NB*128*128];

__device__ __forceinline__ float tanh_fast(float x) {
    float y;
    asm("tanh.approx.f32 %0, %1;" : "=f"(y) : "f"(x));
    return y;
}
__device__ __forceinline__ float sigmoid_fast(float x) {
    return fmaf(0.5f, tanh_fast(0.5f * x), 0.5f);
}
__device__ __forceinline__ __half2 tanh2h(__half2 a) {
    __half2 r;
    asm("tanh.approx.f16x2 %0, %1;" : "=r"(*(unsigned*)&r) : "r"(*(unsigned*)&a));
    return r;
}

__global__ __launch_bounds__(128) void k_alpha(
    const float* __restrict__ attri, const float* __restrict__ w1,
    const float* __restrict__ b1, const float* __restrict__ w2,
    const float* __restrict__ b2)
{
    __shared__ float sv[128];
    __shared__ float sred;
    int d = threadIdx.x;
    float ar[64];
    #pragma unroll
    for (int t = 0; t < 64; ++t) ar[t] = attri[d*64 + t];
    float s = b2[0];
    for (int j = 0; j < 32; ++j) {
        float a = b1[j];
        #pragma unroll
        for (int t = 0; t < 64; ++t) a = fmaf(ar[t], w1[t*32 + j], a);
        a = (a > 0.f) ? a : 0.5f * a;
        s = fmaf(a, w2[j], s);
    }
    sv[d] = s; __syncthreads();
    if (d == 0) { float m = sv[0]; for (int i = 1; i < 128; ++i) m = fmaxf(m, sv[i]); sred = m; }
    __syncthreads();
    float ev = __expf(s - sred);
    sv[d] = ev; __syncthreads();
    if (d == 0) { float su = 0.f; for (int i = 0; i < 128; ++i) su += sv[i]; sred = su; }
    __syncthreads();
    g_alpha[d] = ev / sred;
}

__global__ __launch_bounds__(256) void k_prep(
    const float* __restrict__ X, const float* __restrict__ w_ih,
    const float* __restrict__ w_hh, const float* __restrict__ w_a1,
    const float* __restrict__ b_ih, const float* __restrict__ b_hh)
{
    int i = blockIdx.x * 256 + threadIdx.x;
    if (i < NB*NT*ND) {
        float v = X[i] * g_alpha[i & 127];
        g_Xa[i] = v;
        g_Xh[i] = __float2half(v);
    }
    if (i < 65536) {
        g_wihh[i] = __float2half(w_ih[i]);
        int g = i >> 7, k = i & 127;
        g_whhT[k*512 + g] = __float2half(w_hh[i]);
    }
    if (i < 32768) g_W1hc[i] = __float2half(w_a1[i]);
    if (i < 8192)  g_W1x[i]  = __float2half(w_a1[32768 + i]);
    if (i < 512)   g_bsum[i] = b_ih[i] + b_hh[i];
}

__global__ __launch_bounds__(256) void k_gih()
{
    int m0 = blockIdx.x * 16;
    int w = threadIdx.x >> 5;
    wmma::fragment<wmma::matrix_a, 16, 16, 16, __half, wmma::row_major> a[8];
    #pragma unroll
    for (int k = 0; k < 8; ++k)
        wmma::load_matrix_sync(a[k], g_Xh + (size_t)m0*128 + k*16, 128);
    #pragma unroll
    for (int rep = 0; rep < 4; ++rep) {
        int n0 = w*16 + rep*128;
        wmma::fragment<wmma::accumulator, 16, 16, 16, float> c;
        wmma::fill_fragment(c, 0.f);
        #pragma unroll
        for (int k = 0; k < 8; ++k) {
            wmma::fragment<wmma::matrix_b, 16, 16, 16, __half, wmma::col_major> b;
            wmma::load_matrix_sync(b, g_wihh + (size_t)n0*128 + k*16, 128);
            wmma::mma_sync(c, a[k], b, c);
        }
        wmma::store_matrix_sync(g_gih + (size_t)m0*512 + n0, c, 512, wmma::mem_row_major);
    }
}

__global__ __launch_bounds__(256) void k_xpw()
{
    __shared__ float cbuf[8][256];
    int b = blockIdx.x;
    int w = threadIdx.x >> 5, lane = threadIdx.x & 31;
    const __half* Ab = g_Xh + (size_t)b * (NT*ND);
    int m0 = w * 16;
    wmma::fragment<wmma::matrix_a, 16, 16, 16, __half, wmma::col_major> a[4];
    #pragma unroll
    for (int k = 0; k < 4; ++k)
        wmma::load_matrix_sync(a[k], Ab + k*16*128 + m0, 128);
    for (int nt = 0; nt < 8; ++nt) {
        int n0 = nt * 16;
        wmma::fragment<wmma::accumulator, 16, 16, 16, float> c;
        wmma::fill_fragment(c, 0.f);
        #pragma unroll
        for (int k = 0; k < 4; ++k) {
            wmma::fragment<wmma::matrix_b, 16, 16, 16, __half, wmma::row_major> bb;
            wmma::load_matrix_sync(bb, g_W1x + k*16*128 + n0, 128);
            wmma::mma_sync(c, a[k], bb, c);
        }
        wmma::store_matrix_sync(cbuf[w], c, 16, wmma::mem_row_major);
        __syncwarp();
        #pragma unroll
        for (int j = 0; j < 8; ++j) {
            int idx = j*32 + lane, r = idx >> 4, cl = idx & 15;
            g_XpW[(size_t)b*16384 + (size_t)(m0 + r)*128 + n0 + cl] = __float2half(cbuf[w][idx]);
        }
        __syncwarp();
    }
}

// k_main: single merged mma phase, 2 barriers/step, pipelined phase B
#define SW_WHH 520
#define SW_HA  264
#define SW_GS  516
#define SW_VT  260
#define SW_VH  132
#define OFF_WHH  0
#define OFF_HA   133120
#define OFF_GSC  141568
#define OFF_VTM  174592
#define OFF_VH   191232
#define OFF_BSUM 192288
#define OFF_BA1  194336
#define OFF_WA2  194848
#define OFF_RED  195360
#define SMEM_TOTAL 195488

__global__ __launch_bounds__(512, 1) void k_main(
    const float* __restrict__ b_a1, const float* __restrict__ w_a2,
    const float* __restrict__ b_a2p, float* __restrict__ out)
{
    extern __shared__ char sm[];
    __half* s_whh  = (__half*)(sm + OFF_WHH);
    __half* s_hA   = (__half*)(sm + OFF_HA);
    float*  s_gsc  = (float*)(sm + OFF_GSC);
    float*  s_vtm  = (float*)(sm + OFF_VTM);
    __half* s_vh   = (__half*)(sm + OFF_VH);
    float*  s_bsum = (float*)(sm + OFF_BSUM);
    float*  s_ba1  = (float*)(sm + OFF_BA1);
    float*  s_wa2  = (float*)(sm + OFF_WA2);
    float*  s_red  = (float*)(sm + OFF_RED);

    const int tid = threadIdx.x, w = tid >> 5, lane = tid & 31;
    const int b0 = blockIdx.x * 4;
    const float b_a2 = b_a2p[0];

    {
        const unsigned* s1 = (const unsigned*)g_whhT;
        unsigned* d1 = (unsigned*)s_whh;
        for (int u = tid; u < 32768; u += 512)
            d1[(u >> 8)*260 + (u & 255)] = s1[u];
        unsigned* hz = (unsigned*)s_hA;
        for (int u = tid; u < 2112; u += 512) hz[u] = 0u;
        s_bsum[tid] = g_bsum[tid];
        if (tid < 128) { s_ba1[tid] = b_a1[tid]; s_wa2[tid] = w_a2[tid]; }
    }
    const int b4 = tid >> 7, i = tid & 127;
    const int wq = (tid >> 5) & 3;
    const int vn0 = (w & 7) * 16;
    const int vkh = w >> 3;

    __half2 xp[64];
    {
        const __half2* xr = (const __half2*)(g_XpW + ((size_t)(b0 + b4)*128 + i)*128);
        #pragma unroll
        for (int j = 0; j < 64; ++j) xp[j] = xr[j];
    }
    __syncthreads();

    float creg = 0.f, ex = 0.f, pxa = 0.f;
    size_t poidx = 0;

    for (int t = 0; t < 64; ++t) {
        const size_t grow = ((size_t)(b0 + b4)*64 + t)*512;
        float gp0 = g_gih[grow + i];
        float gp1 = g_gih[grow + 128 + i];
        float gp2 = g_gih[grow + 256 + i];
        float gp3 = g_gih[grow + 384 + i];
        size_t oidx = ((size_t)(b0 + b4)*64 + t)*128 + i;
        float xa = g_Xa[oidx];

        // merged mma phase (old state): gate tiles
        {
            wmma::fragment<wmma::accumulator, 16, 16, 16, float> c0, c1;
            wmma::fill_fragment(c0, 0.f);
            wmma::fill_fragment(c1, 0.f);
            #pragma unroll
            for (int k = 0; k < 8; ++k) {
                wmma::fragment<wmma::matrix_a, 16, 16, 16, __half, wmma::row_major> a;
                wmma::fragment<wmma::matrix_b, 16, 16, 16, __half, wmma::row_major> b;
                wmma::load_matrix_sync(a, s_hA + k*16, SW_HA);
                wmma::load_matrix_sync(b, s_whh + (k*16)*SW_WHH + w*16, SW_WHH);
                wmma::mma_sync(c0, a, b, c0);
                wmma::load_matrix_sync(b, s_whh + (k*16)*SW_WHH + 256 + w*16, SW_WHH);
                wmma::mma_sync(c1, a, b, c1);
            }
            wmma::store_matrix_sync(s_gsc + w*16, c0, SW_GS, wmma::mem_row_major);
            wmma::store_matrix_sync(s_gsc + 256 + w*16, c1, SW_GS, wmma::mem_row_major);
        }
        // v tile (B from global/L2, weights time-invariant)
        {
            wmma::fragment<wmma::accumulator, 16, 16, 16, float> cv;
            wmma::fill_fragment(cv, 0.f);
            #pragma unroll
            for (int k = 0; k < 8; ++k) {
                wmma::fragment<wmma::matrix_a, 16, 16, 16, __half, wmma::row_major> av;
                wmma::fragment<wmma::matrix_b, 16, 16, 16, __half, wmma::row_major> bv;
                wmma::load_matrix_sync(av, s_hA + vkh*128 + k*16, SW_HA);
                wmma::load_matrix_sync(bv, g_W1hc + (size_t)(vkh*128 + k*16)*128 + vn0, 128);
                wmma::mma_sync(cv, av, bv, cv);
            }
            wmma::store_matrix_sync(s_vtm + vkh*128 + vn0, cv, SW_VT, wmma::mem_row_major);
        }

        // phase B part 1 (for step t-1): overlaps mma across warps
        if (t > 0) {
            const __half2* vr = (const __half2*)(s_vh + b4*SW_VH);
            float acc = b_a2;
            #pragma unroll 16
            for (int k2 = 0; k2 < 64; ++k2) {
                __half2 th = tanh2h(__hadd2(xp[k2], vr[k2]));
                float2 tf = __half22float2(th);
                float2 ww = ((const float2*)s_wa2)[k2];
                acc = fmaf(tf.x, ww.x, fmaf(tf.y, ww.y, acc));
            }
            ex = __expf(acc);
            float ss = ex;
            #pragma unroll
            for (int o = 16; o > 0; o >>= 1) ss += __shfl_xor_sync(0xffffffffu, ss, o);
            if (lane == 0) s_red[((t - 1) & 1)*16 + b4*4 + wq] = ss;
        }
        __syncthreads();   // barrier A: gsc/vtm + s_red ready

        if (t > 0) {
            const float* rp = s_red + ((t - 1) & 1)*16 + b4*4;
            float tot = rp[0] + rp[1] + rp[2] + rp[3];
            out[poidx] = (ex / tot) * pxa;
        }

        // epilogue: gates + state update + gv
        {
            float gi = s_gsc[b4*SW_GS + i]       + gp0 + s_bsum[i];
            float gf = s_gsc[b4*SW_GS + 128 + i] + gp1 + s_bsum[128 + i];
            float gg = s_gsc[b4*SW_GS + 256 + i] + gp2 + s_bsum[256 + i];
            float go = s_gsc[b4*SW_GS + 384 + i] + gp3 + s_bsum[384 + i];
            float gv = s_vtm[b4*SW_VT + i] + s_vtm[b4*SW_VT + 128 + i] + s_ba1[i];
            creg = sigmoid_fast(gf)*creg + sigmoid_fast(gi)*tanh_fast(gg);
            float hn = sigmoid_fast(go) * tanh_fast(creg);
            s_hA[b4*SW_HA + i]       = __float2half(hn);
            s_hA[b4*SW_HA + 128 + i] = __float2half(creg);
            s_vh[b4*SW_VH + i]       = __float2half(gv);
        }
        pxa = xa;
        poidx = oidx;
        __syncthreads();   // barrier B: hA/vh ready
    }

    // flush phase B for t = 63
    {
        const __half2* vr = (const __half2*)(s_vh + b4*SW_VH);
        float acc = b_a2;
        #pragma unroll 16
        for (int k2 = 0; k2 < 64; ++k2) {
            __half2 th = tanh2h(__hadd2(xp[k2], vr[k2]));
            float2 tf = __half22float2(th);
            float2 ww = ((const float2*)s_wa2)[k2];
            acc = fmaf(tf.x, ww.x, fmaf(tf.y, ww.y, acc));
        }
        ex = __expf(acc);
        float ss = ex;
        #pragma unroll
        for (int o = 16; o > 0; o >>= 1) ss += __shfl_xor_sync(0xffffffffu, ss, o);
        if (lane == 0) s_red[(63 & 1)*16 + b4*4 + wq] = ss;
        __syncthreads();
        const float* rp = s_red + (63 & 1)*16 + b4*4;
        float tot = rp[0] + rp[1] + rp[2] + rp[3];
        out[poidx] = (ex / tot) * pxa;
    }
}

extern "C" void kernel_launch(void* const* d_in, const int* in_sizes, int n_in,
                              void* d_out, int out_size)
{
    const float* X     = (const float*)d_in[0];
    const float* attri = (const float*)d_in[1];
    const float* w_at1 = (const float*)d_in[2];
    const float* b_at1 = (const float*)d_in[3];
    const float* w_at2 = (const float*)d_in[4];
    const float* b_at2 = (const float*)d_in[5];
    const float* w_a1  = (const float*)d_in[6];
    const float* b_a1  = (const float*)d_in[7];
    const float* w_a2  = (const float*)d_in[8];
    const float* b_a2  = (const float*)d_in[9];
    const float* w_ih  = (const float*)d_in[10];
    const float* w_hh  = (const float*)d_in[11];
    const float* b_ih  = (const float*)d_in[12];
    const float* b_hh  = (const float*)d_in[13];
    float* out = (float*)d_out;

    cudaFuncSetAttribute(k_main, cudaFuncAttributeMaxDynamicSharedMemorySize, SMEM_TOTAL);
    k_alpha<<<1, 128>>>(attri, w_at1, b_at1, w_at2, b_at2);
    k_prep<<<(NB*NT*ND + 255)/256, 256>>>(X, w_ih, w_hh, w_a1, b_ih, b_hh);
    k_gih<<<(NB*NT)/16, 256>>>();
    k_xpw<<<NB, 256>>>();
    k_main<<<128, 512, SMEM_TOTAL>>>(b_a1, w_a2, b_a2, out);
}

// round 9
// speedup vs baseline: 1.2562x; 1.2562x over previous
#include <cuda_runtime.h>
#include <cuda_fp16.h>
#include <mma.h>
using namespace nvcuda;

#define NB 512
#define NT 64
#define ND 128
#define NH 128

__device__ float  g_alpha[128];
__device__ __align__(16) float  g_Xa[NB*NT*ND];
__device__ __align__(16) __half g_Xh[NB*NT*ND];
__device__ __align__(16) __half g_wihh[512*128];
__device__ __align__(16) __half g_whhT[128*512];   // [k][g]
__device__ __align__(16) __half g_W1hc[256*128];   // [j][n]
__device__ __align__(16) __half g_W1x[64*128];
__device__ __align__(16) float  g_bsum[512];
__device__ __align__(16) float  g_gih[(size_t)NB*NT*512];
__device__ __align__(16) __half g_XpW[(size_t)NB*128*128];

__device__ __forceinline__ float tanh_fast(float x) {
    float y;
    asm("tanh.approx.f32 %0, %1;" : "=f"(y) : "f"(x));
    return y;
}
__device__ __forceinline__ float sigmoid_fast(float x) {
    return fmaf(0.5f, tanh_fast(0.5f * x), 0.5f);
}
__device__ __forceinline__ __half2 tanh2h(__half2 a) {
    __half2 r;
    asm("tanh.approx.f16x2 %0, %1;" : "=r"(*(unsigned*)&r) : "r"(*(unsigned*)&a));
    return r;
}

__global__ __launch_bounds__(128) void k_alpha(
    const float* __restrict__ attri, const float* __restrict__ w1,
    const float* __restrict__ b1, const float* __restrict__ w2,
    const float* __restrict__ b2)
{
    __shared__ float sv[128];
    __shared__ float sred;
    int d = threadIdx.x;
    float ar[64];
    #pragma unroll
    for (int t = 0; t < 64; ++t) ar[t] = attri[d*64 + t];
    float s = b2[0];
    for (int j = 0; j < 32; ++j) {
        float a = b1[j];
        #pragma unroll
        for (int t = 0; t < 64; ++t) a = fmaf(ar[t], w1[t*32 + j], a);
        a = (a > 0.f) ? a : 0.5f * a;
        s = fmaf(a, w2[j], s);
    }
    sv[d] = s; __syncthreads();
    if (d == 0) { float m = sv[0]; for (int i = 1; i < 128; ++i) m = fmaxf(m, sv[i]); sred = m; }
    __syncthreads();
    float ev = __expf(s - sred);
    sv[d] = ev; __syncthreads();
    if (d == 0) { float su = 0.f; for (int i = 0; i < 128; ++i) su += sv[i]; sred = su; }
    __syncthreads();
    g_alpha[d] = ev / sred;
}

__global__ __launch_bounds__(256) void k_prep(
    const float* __restrict__ X, const float* __restrict__ w_ih,
    const float* __restrict__ w_hh, const float* __restrict__ w_a1,
    const float* __restrict__ b_ih, const float* __restrict__ b_hh)
{
    int i = blockIdx.x * 256 + threadIdx.x;
    if (i < NB*NT*ND) {
        float v = X[i] * g_alpha[i & 127];
        g_Xa[i] = v;
        g_Xh[i] = __float2half(v);
    }
    if (i < 65536) {
        g_wihh[i] = __float2half(w_ih[i]);
        int g = i >> 7, k = i & 127;
        g_whhT[k*512 + g] = __float2half(w_hh[i]);
    }
    if (i < 32768) g_W1hc[i] = __float2half(w_a1[i]);
    if (i < 8192)  g_W1x[i]  = __float2half(w_a1[32768 + i]);
    if (i < 512)   g_bsum[i] = b_ih[i] + b_hh[i];
}

__global__ __launch_bounds__(256) void k_gih()
{
    int m0 = blockIdx.x * 16;
    int w = threadIdx.x >> 5;
    wmma::fragment<wmma::matrix_a, 16, 16, 16, __half, wmma::row_major> a[8];
    #pragma unroll
    for (int k = 0; k < 8; ++k)
        wmma::load_matrix_sync(a[k], g_Xh + (size_t)m0*128 + k*16, 128);
    #pragma unroll
    for (int rep = 0; rep < 4; ++rep) {
        int n0 = w*16 + rep*128;
        wmma::fragment<wmma::accumulator, 16, 16, 16, float> c;
        wmma::fill_fragment(c, 0.f);
        #pragma unroll
        for (int k = 0; k < 8; ++k) {
            wmma::fragment<wmma::matrix_b, 16, 16, 16, __half, wmma::col_major> b;
            wmma::load_matrix_sync(b, g_wihh + (size_t)n0*128 + k*16, 128);
            wmma::mma_sync(c, a[k], b, c);
        }
        wmma::store_matrix_sync(g_gih + (size_t)m0*512 + n0, c, 512, wmma::mem_row_major);
    }
}

__global__ __launch_bounds__(256) void k_xpw()
{
    __shared__ float cbuf[8][256];
    int b = blockIdx.x;
    int w = threadIdx.x >> 5, lane = threadIdx.x & 31;
    const __half* Ab = g_Xh + (size_t)b * (NT*ND);
    int m0 = w * 16;
    wmma::fragment<wmma::matrix_a, 16, 16, 16, __half, wmma::col_major> a[4];
    #pragma unroll
    for (int k = 0; k < 4; ++k)
        wmma::load_matrix_sync(a[k], Ab + k*16*128 + m0, 128);
    for (int nt = 0; nt < 8; ++nt) {
        int n0 = nt * 16;
        wmma::fragment<wmma::accumulator, 16, 16, 16, float> c;
        wmma::fill_fragment(c, 0.f);
        #pragma unroll
        for (int k = 0; k < 4; ++k) {
            wmma::fragment<wmma::matrix_b, 16, 16, 16, __half, wmma::row_major> bb;
            wmma::load_matrix_sync(bb, g_W1x + k*16*128 + n0, 128);
            wmma::mma_sync(c, a[k], bb, c);
        }
        wmma::store_matrix_sync(cbuf[w], c, 16, wmma::mem_row_major);
        __syncwarp();
        #pragma unroll
        for (int j = 0; j < 8; ++j) {
            int idx = j*32 + lane, r = idx >> 4, cl = idx & 15;
            g_XpW[(size_t)b*16384 + (size_t)(m0 + r)*128 + n0 + cl] = __float2half(cbuf[w][idx]);
        }
        __syncwarp();
    }
}

// k_main: R6 phases + phase-B(t-1) chunks interleaved, double-buffered vh/red
#define SW_WHH 520
#define SW_W1  136
#define SW_HA  264
#define SW_GS  260
#define SW_VH  132
#define OFF_WHH  0
#define OFF_W1   133120
#define OFF_HA   202752
#define OFF_GSC  211200
#define OFF_VH   227840
#define OFF_WA2  229952
#define OFF_RED  230464
#define SMEM_TOTAL 230592

__global__ __launch_bounds__(512, 1) void k_main(
    const float* __restrict__ b_a1, const float* __restrict__ w_a2,
    const float* __restrict__ b_a2p, float* __restrict__ out)
{
    extern __shared__ char sm[];
    __half* s_whh = (__half*)(sm + OFF_WHH);
    __half* s_w1  = (__half*)(sm + OFF_W1);
    __half* s_hA  = (__half*)(sm + OFF_HA);
    float*  s_gsc = (float*)(sm + OFF_GSC);
    __half* s_vh  = (__half*)(sm + OFF_VH);
    float*  s_wa2 = (float*)(sm + OFF_WA2);
    float*  s_red = (float*)(sm + OFF_RED);

    const int tid = threadIdx.x, w = tid >> 5, lane = tid & 31;
    const int b0 = blockIdx.x * 4;
    const float b_a2 = b_a2p[0];

    {
        const unsigned* s1 = (const unsigned*)g_whhT;
        unsigned* d1 = (unsigned*)s_whh;
        for (int u = tid; u < 32768; u += 512)
            d1[(u >> 8)*260 + (u & 255)] = s1[u];
        const unsigned* s2 = (const unsigned*)g_W1hc;
        unsigned* d2 = (unsigned*)s_w1;
        for (int u = tid; u < 16384; u += 512)
            d2[(u >> 6)*68 + (u & 63)] = s2[u];
        unsigned* hz = (unsigned*)s_hA;
        for (int u = tid; u < 2112; u += 512) hz[u] = 0u;
        if (tid < 128) s_wa2[tid] = w_a2[tid];
    }
    const int b4 = tid >> 7, i = tid & 127;
    const int wq = (tid >> 5) & 3;
    const int vn0 = (w & 7) * 16;
    const int vkh = w >> 3;

    __half2 xp[64];
    {
        const __half2* xr = (const __half2*)(g_XpW + ((size_t)(b0 + b4)*128 + i)*128);
        #pragma unroll
        for (int j = 0; j < 64; ++j) xp[j] = xr[j];
    }
    __syncthreads();

    float creg = 0.f, iis = 0.f, ffc = 0.f;
    float ex = 0.f, pxa = 0.f;
    size_t poidx = 0;

    for (int t = 0; t < 64; ++t) {
        const size_t grow = ((size_t)(b0 + b4)*64 + t)*512;
        float gp0 = g_gih[grow + i];
        float gp1 = g_gih[grow + 128 + i];
        float gp2 = g_gih[grow + 256 + i];
        float gp3 = g_gih[grow + 384 + i];
        float bs0 = __ldg(&g_bsum[i]);
        float bs1 = __ldg(&g_bsum[128 + i]);
        float bs2 = __ldg(&g_bsum[256 + i]);
        float bs3 = __ldg(&g_bsum[384 + i]);
        float ba1i = __ldg(&b_a1[i]);
        size_t oidx = ((size_t)(b0 + b4)*64 + t)*128 + i;
        float xa = g_Xa[oidx];

        float acc = b_a2;
        const __half2* vr = (const __half2*)(s_vh + ((t - 1) & 1)*528 + b4*SW_VH);

        // P1: V = [h|c] @ W1hc  -> gsc
        {
            wmma::fragment<wmma::accumulator, 16, 16, 16, float> c;
            wmma::fill_fragment(c, 0.f);
            #pragma unroll
            for (int k = 0; k < 8; ++k) {
                wmma::fragment<wmma::matrix_a, 16, 16, 16, __half, wmma::row_major> a;
                wmma::fragment<wmma::matrix_b, 16, 16, 16, __half, wmma::row_major> b;
                wmma::load_matrix_sync(a, s_hA + vkh*128 + k*16, SW_HA);
                wmma::load_matrix_sync(b, s_w1 + (vkh*128 + k*16)*SW_W1 + vn0, SW_W1);
                wmma::mma_sync(c, a, b, c);
            }
            wmma::store_matrix_sync(s_gsc + vkh*128 + vn0, c, SW_GS, wmma::mem_row_major);
        }
        if (t > 0) {
            #pragma unroll
            for (int k2 = 0; k2 < 16; ++k2) {
                __half2 th = tanh2h(__hadd2(xp[k2], vr[k2]));
                float2 tf = __half22float2(th);
                float2 ww = ((const float2*)s_wa2)[k2];
                acc = fmaf(tf.x, ww.x, fmaf(tf.y, ww.y, acc));
            }
        }
        __syncthreads();

        // E1: gv -> vh[t&1]
        {
            float gv = s_gsc[b4*SW_GS + i] + s_gsc[b4*SW_GS + 128 + i] + ba1i;
            s_vh[(t & 1)*528 + b4*SW_VH + i] = __float2half(gv);
        }
        if (t > 0) {
            #pragma unroll
            for (int k2 = 16; k2 < 24; ++k2) {
                __half2 th = tanh2h(__hadd2(xp[k2], vr[k2]));
                float2 tf = __half22float2(th);
                float2 ww = ((const float2*)s_wa2)[k2];
                acc = fmaf(tf.x, ww.x, fmaf(tf.y, ww.y, acc));
            }
        }
        __syncthreads();

        // P2: IF gates (cols 0..255)
        {
            wmma::fragment<wmma::accumulator, 16, 16, 16, float> c;
            wmma::fill_fragment(c, 0.f);
            #pragma unroll
            for (int k = 0; k < 8; ++k) {
                wmma::fragment<wmma::matrix_a, 16, 16, 16, __half, wmma::row_major> a;
                wmma::fragment<wmma::matrix_b, 16, 16, 16, __half, wmma::row_major> b;
                wmma::load_matrix_sync(a, s_hA + k*16, SW_HA);
                wmma::load_matrix_sync(b, s_whh + (k*16)*SW_WHH + w*16, SW_WHH);
                wmma::mma_sync(c, a, b, c);
            }
            wmma::store_matrix_sync(s_gsc + w*16, c, SW_GS, wmma::mem_row_major);
        }
        if (t > 0) {
            #pragma unroll
            for (int k2 = 24; k2 < 40; ++k2) {
                __half2 th = tanh2h(__hadd2(xp[k2], vr[k2]));
                float2 tf = __half22float2(th);
                float2 ww = ((const float2*)s_wa2)[k2];
                acc = fmaf(tf.x, ww.x, fmaf(tf.y, ww.y, acc));
            }
        }
        __syncthreads();

        // E2: i,f gates
        {
            float gi = s_gsc[b4*SW_GS + i]       + gp0 + bs0;
            float gf = s_gsc[b4*SW_GS + 128 + i] + gp1 + bs1;
            iis = sigmoid_fast(gi);
            ffc = sigmoid_fast(gf) * creg;
        }
        if (t > 0) {
            #pragma unroll
            for (int k2 = 40; k2 < 48; ++k2) {
                __half2 th = tanh2h(__hadd2(xp[k2], vr[k2]));
                float2 tf = __half22float2(th);
                float2 ww = ((const float2*)s_wa2)[k2];
                acc = fmaf(tf.x, ww.x, fmaf(tf.y, ww.y, acc));
            }
        }
        __syncthreads();

        // P3: GO gates (cols 256..511)
        {
            wmma::fragment<wmma::accumulator, 16, 16, 16, float> c;
            wmma::fill_fragment(c, 0.f);
            #pragma unroll
            for (int k = 0; k < 8; ++k) {
                wmma::fragment<wmma::matrix_a, 16, 16, 16, __half, wmma::row_major> a;
                wmma::fragment<wmma::matrix_b, 16, 16, 16, __half, wmma::row_major> b;
                wmma::load_matrix_sync(a, s_hA + k*16, SW_HA);
                wmma::load_matrix_sync(b, s_whh + (k*16)*SW_WHH + 256 + w*16, SW_WHH);
                wmma::mma_sync(c, a, b, c);
            }
            wmma::store_matrix_sync(s_gsc + w*16, c, SW_GS, wmma::mem_row_major);
        }
        if (t > 0) {
            #pragma unroll
            for (int k2 = 48; k2 < 64; ++k2) {
                __half2 th = tanh2h(__hadd2(xp[k2], vr[k2]));
                float2 tf = __half22float2(th);
                float2 ww = ((const float2*)s_wa2)[k2];
                acc = fmaf(tf.x, ww.x, fmaf(tf.y, ww.y, acc));
            }
            ex = __expf(acc);
            float ss = ex;
            #pragma unroll
            for (int o = 16; o > 0; o >>= 1) ss += __shfl_xor_sync(0xffffffffu, ss, o);
            if (lane == 0) s_red[((t - 1) & 1)*16 + b4*4 + wq] = ss;
        }
        __syncthreads();

        // E3: g,o gates + state update + out(t-1)
        {
            float gg = s_gsc[b4*SW_GS + i]       + gp2 + bs2;
            float go = s_gsc[b4*SW_GS + 128 + i] + gp3 + bs3;
            creg = ffc + iis * tanh_fast(gg);
            float hn = sigmoid_fast(go) * tanh_fast(creg);
            s_hA[b4*SW_HA + i]       = __float2half(hn);
            s_hA[b4*SW_HA + 128 + i] = __float2half(creg);
        }
        if (t > 0) {
            const float* rp = s_red + ((t - 1) & 1)*16 + b4*4;
            float tot = rp[0] + rp[1] + rp[2] + rp[3];
            out[poidx] = (ex / tot) * pxa;
        }
        pxa = xa;
        poidx = oidx;
        __syncthreads();
    }

    // flush phase B for t = 63
    {
        const __half2* vr = (const __half2*)(s_vh + (63 & 1)*528 + b4*SW_VH);
        float acc = b_a2;
        #pragma unroll 16
        for (int k2 = 0; k2 < 64; ++k2) {
            __half2 th = tanh2h(__hadd2(xp[k2], vr[k2]));
            float2 tf = __half22float2(th);
            float2 ww = ((const float2*)s_wa2)[k2];
            acc = fmaf(tf.x, ww.x, fmaf(tf.y, ww.y, acc));
        }
        ex = __expf(acc);
        float ss = ex;
        #pragma unroll
        for (int o = 16; o > 0; o >>= 1) ss += __shfl_xor_sync(0xffffffffu, ss, o);
        if (lane == 0) s_red[(63 & 1)*16 + b4*4 + wq] = ss;
        __syncthreads();
        const float* rp = s_red + (63 & 1)*16 + b4*4;
        float tot = rp[0] + rp[1] + rp[2] + rp[3];
        out[poidx] = (ex / tot) * pxa;
    }
}

extern "C" void kernel_launch(void* const* d_in, const int* in_sizes, int n_in,
                              void* d_out, int out_size)
{
    const float* X     = (const float*)d_in[0];
    const float* attri = (const float*)d_in[1];
    const float* w_at1 = (const float*)d_in[2];
    const float* b_at1 = (const float*)d_in[3];
    const float* w_at2 = (const float*)d_in[4];
    const float* b_at2 = (const float*)d_in[5];
    const float* w_a1  = (const float*)d_in[6];
    const float* b_a1  = (const float*)d_in[7];
    const float* w_a2  = (const float*)d_in[8];
    const float* b_a2  = (const float*)d_in[9];
    const float* w_ih  = (const float*)d_in[10];
    const float* w_hh  = (const float*)d_in[11];
    const float* b_ih  = (const float*)d_in[12];
    const float* b_hh  = (const float*)d_in[13];
    float* out = (float*)d_out;

    cudaFuncSetAttribute(k_main, cudaFuncAttributeMaxDynamicSharedMemorySize, SMEM_TOTAL);
    k_alpha<<<1, 128>>>(attri, w_at1, b_at1, w_at2, b_at2);
    k_prep<<<(NB*NT*ND + 255)/256, 256>>>(X, w_ih, w_hh, w_a1, b_ih, b_hh);
    k_gih<<<(NB*NT)/16, 256>>>();
    k_xpw<<<NB, 256>>>();
    k_main<<<128, 512, SMEM_TOTAL>>>(b_a1, w_a2, b_a2, out);
}

// round 10
// speedup vs baseline: 1.3203x; 1.0511x over previous
#include <cuda_runtime.h>
#include <cuda_fp16.h>
#include <mma.h>
using namespace nvcuda;

#define NB 512
#define NT 64
#define ND 128
#define NH 128

__device__ float  g_alpha[128];
__device__ __align__(16) float  g_Xa[NB*NT*ND];
__device__ __align__(16) __half g_Xh[NB*NT*ND];
__device__ __align__(16) __half g_wihh[512*128];
__device__ __align__(16) __half g_whhT[128*512];   // [k][g]
__device__ __align__(16) __half g_W1hc[256*128];   // [j][n]
__device__ __align__(16) __half g_W1x[64*128];
__device__ __align__(16) float  g_bsum[512];
__device__ __align__(16) float  g_gih[(size_t)NB*NT*512];
__device__ __align__(16) __half g_XpW[(size_t)NB*128*128];

__device__ __forceinline__ float tanh_fast(float x) {
    float y;
    asm("tanh.approx.f32 %0, %1;" : "=f"(y) : "f"(x));
    return y;
}
__device__ __forceinline__ float sigmoid_fast(float x) {
    return fmaf(0.5f, tanh_fast(0.5f * x), 0.5f);
}
__device__ __forceinline__ __half2 tanh2h(__half2 a) {
    __half2 r;
    asm("tanh.approx.f16x2 %0, %1;" : "=r"(*(unsigned*)&r) : "r"(*(unsigned*)&a));
    return r;
}

__global__ __launch_bounds__(128) void k_alpha(
    const float* __restrict__ attri, const float* __restrict__ w1,
    const float* __restrict__ b1, const float* __restrict__ w2,
    const float* __restrict__ b2)
{
    __shared__ float sv[128];
    __shared__ float sred;
    int d = threadIdx.x;
    float ar[64];
    #pragma unroll
    for (int t = 0; t < 64; ++t) ar[t] = attri[d*64 + t];
    float s = b2[0];
    for (int j = 0; j < 32; ++j) {
        float a = b1[j];
        #pragma unroll
        for (int t = 0; t < 64; ++t) a = fmaf(ar[t], w1[t*32 + j], a);
        a = (a > 0.f) ? a : 0.5f * a;
        s = fmaf(a, w2[j], s);
    }
    sv[d] = s; __syncthreads();
    if (d == 0) { float m = sv[0]; for (int i = 1; i < 128; ++i) m = fmaxf(m, sv[i]); sred = m; }
    __syncthreads();
    float ev = __expf(s - sred);
    sv[d] = ev; __syncthreads();
    if (d == 0) { float su = 0.f; for (int i = 0; i < 128; ++i) su += sv[i]; sred = su; }
    __syncthreads();
    g_alpha[d] = ev / sred;
}

__global__ __launch_bounds__(256) void k_prep(
    const float* __restrict__ X, const float* __restrict__ w_ih,
    const float* __restrict__ w_hh, const float* __restrict__ w_a1,
    const float* __restrict__ b_ih, const float* __restrict__ b_hh)
{
    int i = blockIdx.x * 256 + threadIdx.x;
    if (i < NB*NT*ND) {
        float v = X[i] * g_alpha[i & 127];
        g_Xa[i] = v;
        g_Xh[i] = __float2half(v);
    }
    if (i < 65536) {
        g_wihh[i] = __float2half(w_ih[i]);
        int g = i >> 7, k = i & 127;
        g_whhT[k*512 + g] = __float2half(w_hh[i]);
    }
    if (i < 32768) g_W1hc[i] = __float2half(w_a1[i]);
    if (i < 8192)  g_W1x[i]  = __float2half(w_a1[32768 + i]);
    if (i < 512)   g_bsum[i] = b_ih[i] + b_hh[i];
}

__global__ __launch_bounds__(256) void k_gih()
{
    int m0 = blockIdx.x * 16;
    int w = threadIdx.x >> 5;
    wmma::fragment<wmma::matrix_a, 16, 16, 16, __half, wmma::row_major> a[8];
    #pragma unroll
    for (int k = 0; k < 8; ++k)
        wmma::load_matrix_sync(a[k], g_Xh + (size_t)m0*128 + k*16, 128);
    #pragma unroll
    for (int rep = 0; rep < 4; ++rep) {
        int n0 = w*16 + rep*128;
        wmma::fragment<wmma::accumulator, 16, 16, 16, float> c;
        wmma::fill_fragment(c, 0.f);
        #pragma unroll
        for (int k = 0; k < 8; ++k) {
            wmma::fragment<wmma::matrix_b, 16, 16, 16, __half, wmma::col_major> b;
            wmma::load_matrix_sync(b, g_wihh + (size_t)n0*128 + k*16, 128);
            wmma::mma_sync(c, a[k], b, c);
        }
        wmma::store_matrix_sync(g_gih + (size_t)m0*512 + n0, c, 512, wmma::mem_row_major);
    }
}

__global__ __launch_bounds__(256) void k_xpw()
{
    __shared__ float cbuf[8][256];
    int b = blockIdx.x;
    int w = threadIdx.x >> 5, lane = threadIdx.x & 31;
    const __half* Ab = g_Xh + (size_t)b * (NT*ND);
    int m0 = w * 16;
    wmma::fragment<wmma::matrix_a, 16, 16, 16, __half, wmma::col_major> a[4];
    #pragma unroll
    for (int k = 0; k < 4; ++k)
        wmma::load_matrix_sync(a[k], Ab + k*16*128 + m0, 128);
    for (int nt = 0; nt < 8; ++nt) {
        int n0 = nt * 16;
        wmma::fragment<wmma::accumulator, 16, 16, 16, float> c;
        wmma::fill_fragment(c, 0.f);
        #pragma unroll
        for (int k = 0; k < 4; ++k) {
            wmma::fragment<wmma::matrix_b, 16, 16, 16, __half, wmma::row_major> bb;
            wmma::load_matrix_sync(bb, g_W1x + k*16*128 + n0, 128);
            wmma::mma_sync(c, a[k], bb, c);
        }
        wmma::store_matrix_sync(cbuf[w], c, 16, wmma::mem_row_major);
        __syncwarp();
        #pragma unroll
        for (int j = 0; j < 8; ++j) {
            int idx = j*32 + lane, r = idx >> 4, cl = idx & 15;
            g_XpW[(size_t)b*16384 + (size_t)(m0 + r)*128 + n0 + cl] = __float2half(cbuf[w][idx]);
        }
        __syncwarp();
    }
}

// k_main: m8n32k16, single merged mma phase, 2 barriers/step
#define B1W  648
#define B2W  136
#define HAW  264
#define SGW  780
#define OFF_B1   0
#define OFF_B2   165888
#define OFF_HA   200704
#define OFF_GSC  204928
#define OFF_VH   229888
#define OFF_RED  232000
#define OFF_WA2  232128
#define SMEM_TOTAL 232384

__global__ __launch_bounds__(512, 1) void k_main(
    const float* __restrict__ b_a1, const float* __restrict__ w_a2,
    const float* __restrict__ b_a2p, float* __restrict__ out)
{
    extern __shared__ char sm[];
    __half* s_b1  = (__half*)(sm + OFF_B1);   // [k=128][648]: gates 0..511, W1h 512..639
    __half* s_b2  = (__half*)(sm + OFF_B2);   // [k=128][136]: W1c 0..127
    __half* s_hA  = (__half*)(sm + OFF_HA);   // [8][264]: rows 0..3 = batches, cols h|c
    float*  s_gsc = (float*)(sm + OFF_GSC);   // [8][780]: gates 0..511, vH 512..639, vC 640..767
    __half* s_vh  = (__half*)(sm + OFF_VH);   // 2 x [4][132]
    float*  s_red = (float*)(sm + OFF_RED);   // 2 x 16
    __half2* s_wa2 = (__half2*)(sm + OFF_WA2);

    const int tid = threadIdx.x, w = tid >> 5, lane = tid & 31;
    const int b0 = blockIdx.x * 4;
    const float b_a2 = b_a2p[0];

    {
        const __half2* whh2 = (const __half2*)g_whhT;  // [128][256]
        const __half2* w1a2 = (const __half2*)g_W1hc;  // [256][64]
        __half2* b1 = (__half2*)s_b1;
        for (int u = tid; u < 128*324; u += 512) {
            int k = u / 324, c = u % 324;
            b1[k*324 + c] = (c < 256) ? whh2[k*256 + c] :
                            (c < 320) ? w1a2[k*64 + (c - 256)] : __float2half2_rn(0.f);
        }
        __half2* b2 = (__half2*)s_b2;
        for (int u = tid; u < 128*68; u += 512) {
            int k = u / 68, c = u % 68;
            b2[k*68 + c] = (c < 64) ? w1a2[(128 + k)*64 + c] : __float2half2_rn(0.f);
        }
        __half2* hz = (__half2*)s_hA;
        for (int u = tid; u < 8*132; u += 512) hz[u] = __float2half2_rn(0.f);
        if (tid < 64) s_wa2[tid] = __floats2half2_rn(w_a2[2*tid], w_a2[2*tid + 1]);
    }
    const int b4 = tid >> 7, i = tid & 127;
    const int wq = (tid >> 5) & 3;

    __half2 xp[64];
    {
        const __half2* xr = (const __half2*)(g_XpW + ((size_t)(b0 + b4)*128 + i)*128);
        #pragma unroll
        for (int j = 0; j < 64; ++j) xp[j] = xr[j];
    }
    const float bs0 = g_bsum[i];
    const float bs1 = g_bsum[128 + i];
    const float bs2 = g_bsum[256 + i];
    const float bs3 = g_bsum[384 + i];
    const float ba1i = b_a1[i];
    __syncthreads();

    float creg = 0.f, ex = 0.f, pxa = 0.f;
    size_t poidx = 0;

    for (int t = 0; t < 64; ++t) {
        const size_t grow = ((size_t)(b0 + b4)*64 + t)*512;
        float gp0 = g_gih[grow + i];
        float gp1 = g_gih[grow + 128 + i];
        float gp2 = g_gih[grow + 256 + i];
        float gp3 = g_gih[grow + 384 + i];
        size_t oidx = ((size_t)(b0 + b4)*64 + t)*128 + i;
        float xa = g_Xa[oidx];

        // merged mma phase: gate tile (all 16 warps)
        {
            wmma::fragment<wmma::accumulator, 8, 32, 16, float> c0;
            wmma::fill_fragment(c0, 0.f);
            #pragma unroll
            for (int k = 0; k < 8; ++k) {
                wmma::fragment<wmma::matrix_a, 8, 32, 16, __half, wmma::row_major> a;
                wmma::fragment<wmma::matrix_b, 8, 32, 16, __half, wmma::row_major> b;
                wmma::load_matrix_sync(a, s_hA + k*16, HAW);
                wmma::load_matrix_sync(b, s_b1 + (k*16)*B1W + w*32, B1W);
                wmma::mma_sync(c0, a, b, c0);
            }
            wmma::store_matrix_sync(s_gsc + w*32, c0, SGW, wmma::mem_row_major);
        }
        // v tiles (warps 0..7)
        if (w < 4) {
            wmma::fragment<wmma::accumulator, 8, 32, 16, float> cv;
            wmma::fill_fragment(cv, 0.f);
            #pragma unroll
            for (int k = 0; k < 8; ++k) {
                wmma::fragment<wmma::matrix_a, 8, 32, 16, __half, wmma::row_major> a;
                wmma::fragment<wmma::matrix_b, 8, 32, 16, __half, wmma::row_major> b;
                wmma::load_matrix_sync(a, s_hA + k*16, HAW);
                wmma::load_matrix_sync(b, s_b1 + (k*16)*B1W + 512 + w*32, B1W);
                wmma::mma_sync(cv, a, b, cv);
            }
            wmma::store_matrix_sync(s_gsc + 512 + w*32, cv, SGW, wmma::mem_row_major);
        } else if (w < 8) {
            wmma::fragment<wmma::accumulator, 8, 32, 16, float> cv;
            wmma::fill_fragment(cv, 0.f);
            #pragma unroll
            for (int k = 0; k < 8; ++k) {
                wmma::fragment<wmma::matrix_a, 8, 32, 16, __half, wmma::row_major> a;
                wmma::fragment<wmma::matrix_b, 8, 32, 16, __half, wmma::row_major> b;
                wmma::load_matrix_sync(a, s_hA + 128 + k*16, HAW);
                wmma::load_matrix_sync(b, s_b2 + (k*16)*B2W + (w - 4)*32, B2W);
                wmma::mma_sync(cv, a, b, cv);
            }
            wmma::store_matrix_sync(s_gsc + 640 + (w - 4)*32, cv, SGW, wmma::mem_row_major);
        }

        // phase B for step t-1 (overlaps mma across warps)
        if (t > 0) {
            const __half2* vr = (const __half2*)(s_vh + ((t - 1) & 1)*528 + b4*132);
            float acc = b_a2;
            #pragma unroll 16
            for (int k2 = 0; k2 < 64; ++k2) {
                __half2 th = tanh2h(__hadd2(xp[k2], vr[k2]));
                float2 tf = __half22float2(th);
                float2 ww = __half22float2(s_wa2[k2]);
                acc = fmaf(tf.x, ww.x, fmaf(tf.y, ww.y, acc));
            }
            ex = __expf(acc);
            float ss = ex;
            #pragma unroll
            for (int o = 16; o > 0; o >>= 1) ss += __shfl_xor_sync(0xffffffffu, ss, o);
            if (lane == 0) s_red[((t - 1) & 1)*16 + b4*4 + wq] = ss;
        }
        __syncthreads();

        // epilogue: gates + v + state update + out(t-1)
        {
            const float* gr = s_gsc + b4*SGW;
            float gi = gr[i]       + gp0 + bs0;
            float gf = gr[128 + i] + gp1 + bs1;
            float gg = gr[256 + i] + gp2 + bs2;
            float go = gr[384 + i] + gp3 + bs3;
            float gv = gr[512 + i] + gr[640 + i] + ba1i;
            creg = sigmoid_fast(gf)*creg + sigmoid_fast(gi)*tanh_fast(gg);
            float hn = sigmoid_fast(go) * tanh_fast(creg);
            s_hA[b4*HAW + i]       = __float2half(hn);
            s_hA[b4*HAW + 128 + i] = __float2half(creg);
            s_vh[(t & 1)*528 + b4*132 + i] = __float2half(gv);
        }
        if (t > 0) {
            const float* rp = s_red + ((t - 1) & 1)*16 + b4*4;
            float tot = rp[0] + rp[1] + rp[2] + rp[3];
            out[poidx] = (ex / tot) * pxa;
        }
        pxa = xa;
        poidx = oidx;
        __syncthreads();
    }

    // flush phase B for t = 63
    {
        const __half2* vr = (const __half2*)(s_vh + (63 & 1)*528 + b4*132);
        float acc = b_a2;
        #pragma unroll 16
        for (int k2 = 0; k2 < 64; ++k2) {
            __half2 th = tanh2h(__hadd2(xp[k2], vr[k2]));
            float2 tf = __half22float2(th);
            float2 ww = __half22float2(s_wa2[k2]);
            acc = fmaf(tf.x, ww.x, fmaf(tf.y, ww.y, acc));
        }
        ex = __expf(acc);
        float ss = ex;
        #pragma unroll
        for (int o = 16; o > 0; o >>= 1) ss += __shfl_xor_sync(0xffffffffu, ss, o);
        if (lane == 0) s_red[(63 & 1)*16 + b4*4 + wq] = ss;
        __syncthreads();
        const float* rp = s_red + (63 & 1)*16 + b4*4;
        float tot = rp[0] + rp[1] + rp[2] + rp[3];
        out[poidx] = (ex / tot) * pxa;
    }
}

extern "C" void kernel_launch(void* const* d_in, const int* in_sizes, int n_in,
                              void* d_out, int out_size)
{
    const float* X     = (const float*)d_in[0];
    const float* attri = (const float*)d_in[1];
    const float* w_at1 = (const float*)d_in[2];
    const float* b_at1 = (const float*)d_in[3];
    const float* w_at2 = (const float*)d_in[4];
    const float* b_at2 = (const float*)d_in[5];
    const float* w_a1  = (const float*)d_in[6];
    const float* b_a1  = (const float*)d_in[7];
    const float* w_a2  = (const float*)d_in[8];
    const float* b_a2  = (const float*)d_in[9];
    const float* w_ih  = (const float*)d_in[10];
    const float* w_hh  = (const float*)d_in[11];
    const float* b_ih  = (const float*)d_in[12];
    const float* b_hh  = (const float*)d_in[13];
    float* out = (float*)d_out;

    cudaFuncSetAttribute(k_main, cudaFuncAttributeMaxDynamicSharedMemorySize, SMEM_TOTAL);
    k_alpha<<<1, 128>>>(attri, w_at1, b_at1, w_at2, b_at2);
    k_prep<<<(NB*NT*ND + 255)/256, 256>>>(X, w_ih, w_hh, w_a1, b_ih, b_hh);
    k_gih<<<(NB*NT)/16, 256>>>();
    k_xpw<<<NB, 256>>>();
    k_main<<<128, 512, SMEM_TOTAL>>>(b_a1, w_a2, b_a2, out);
}

// round 11
// speedup vs baseline: 1.4230x; 1.0777x over previous
#include <cuda_runtime.h>
#include <cuda_fp16.h>
#include <mma.h>
using namespace nvcuda;

#define NB 512
#define NT 64
#define ND 128
#define NH 128

__device__ float  g_alpha[128];
__device__ __align__(16) float  g_Xa[NB*NT*ND];
__device__ __align__(16) __half g_Xh[NB*NT*ND];
__device__ __align__(16) __half g_wihh[512*128];
__device__ __align__(16) __half g_whhT[128*512];   // [k][g]
__device__ __align__(16) __half g_W1hc[256*128];   // [j][n]
__device__ __align__(16) __half g_W1x[64*128];
__device__ __align__(16) float  g_bsum[512];
__device__ __align__(16) float  g_gih[(size_t)NB*NT*512];
__device__ __align__(16) __half g_XpW[(size_t)NB*128*128];
__device__ __align__(16) __half g_vh[(size_t)NB*NT*128];   // v per (b,t)

__device__ __forceinline__ float tanh_fast(float x) {
    float y;
    asm("tanh.approx.f32 %0, %1;" : "=f"(y) : "f"(x));
    return y;
}
__device__ __forceinline__ float sigmoid_fast(float x) {
    return fmaf(0.5f, tanh_fast(0.5f * x), 0.5f);
}
__device__ __forceinline__ __half2 tanh2h(__half2 a) {
    __half2 r;
    asm("tanh.approx.f16x2 %0, %1;" : "=r"(*(unsigned*)&r) : "r"(*(unsigned*)&a));
    return r;
}

__global__ __launch_bounds__(128) void k_alpha(
    const float* __restrict__ attri, const float* __restrict__ w1,
    const float* __restrict__ b1, const float* __restrict__ w2,
    const float* __restrict__ b2)
{
    __shared__ float sv[128];
    __shared__ float sred;
    int d = threadIdx.x;
    float ar[64];
    #pragma unroll
    for (int t = 0; t < 64; ++t) ar[t] = attri[d*64 + t];
    float s = b2[0];
    for (int j = 0; j < 32; ++j) {
        float a = b1[j];
        #pragma unroll
        for (int t = 0; t < 64; ++t) a = fmaf(ar[t], w1[t*32 + j], a);
        a = (a > 0.f) ? a : 0.5f * a;
        s = fmaf(a, w2[j], s);
    }
    sv[d] = s; __syncthreads();
    if (d == 0) { float m = sv[0]; for (int i = 1; i < 128; ++i) m = fmaxf(m, sv[i]); sred = m; }
    __syncthreads();
    float ev = __expf(s - sred);
    sv[d] = ev; __syncthreads();
    if (d == 0) { float su = 0.f; for (int i = 0; i < 128; ++i) su += sv[i]; sred = su; }
    __syncthreads();
    g_alpha[d] = ev / sred;
}

__global__ __launch_bounds__(256) void k_prep(
    const float* __restrict__ X, const float* __restrict__ w_ih,
    const float* __restrict__ w_hh, const float* __restrict__ w_a1,
    const float* __restrict__ b_ih, const float* __restrict__ b_hh)
{
    int i = blockIdx.x * 256 + threadIdx.x;
    if (i < NB*NT*ND) {
        float v = X[i] * g_alpha[i & 127];
        g_Xa[i] = v;
        g_Xh[i] = __float2half(v);
    }
    if (i < 65536) {
        g_wihh[i] = __float2half(w_ih[i]);
        int g = i >> 7, k = i & 127;
        g_whhT[k*512 + g] = __float2half(w_hh[i]);
    }
    if (i < 32768) g_W1hc[i] = __float2half(w_a1[i]);
    if (i < 8192)  g_W1x[i]  = __float2half(w_a1[32768 + i]);
    if (i < 512)   g_bsum[i] = b_ih[i] + b_hh[i];
}

__global__ __launch_bounds__(256) void k_gih()
{
    int m0 = blockIdx.x * 16;
    int w = threadIdx.x >> 5;
    wmma::fragment<wmma::matrix_a, 16, 16, 16, __half, wmma::row_major> a[8];
    #pragma unroll
    for (int k = 0; k < 8; ++k)
        wmma::load_matrix_sync(a[k], g_Xh + (size_t)m0*128 + k*16, 128);
    #pragma unroll
    for (int rep = 0; rep < 4; ++rep) {
        int n0 = w*16 + rep*128;
        wmma::fragment<wmma::accumulator, 16, 16, 16, float> c;
        wmma::fill_fragment(c, 0.f);
        #pragma unroll
        for (int k = 0; k < 8; ++k) {
            wmma::fragment<wmma::matrix_b, 16, 16, 16, __half, wmma::col_major> b;
            wmma::load_matrix_sync(b, g_wihh + (size_t)n0*128 + k*16, 128);
            wmma::mma_sync(c, a[k], b, c);
        }
        wmma::store_matrix_sync(g_gih + (size_t)m0*512 + n0, c, 512, wmma::mem_row_major);
    }
}

__global__ __launch_bounds__(256) void k_xpw()
{
    __shared__ float cbuf[8][256];
    int b = blockIdx.x;
    int w = threadIdx.x >> 5, lane = threadIdx.x & 31;
    const __half* Ab = g_Xh + (size_t)b * (NT*ND);
    int m0 = w * 16;
    wmma::fragment<wmma::matrix_a, 16, 16, 16, __half, wmma::col_major> a[4];
    #pragma unroll
    for (int k = 0; k < 4; ++k)
        wmma::load_matrix_sync(a[k], Ab + k*16*128 + m0, 128);
    for (int nt = 0; nt < 8; ++nt) {
        int n0 = nt * 16;
        wmma::fragment<wmma::accumulator, 16, 16, 16, float> c;
        wmma::fill_fragment(c, 0.f);
        #pragma unroll
        for (int k = 0; k < 4; ++k) {
            wmma::fragment<wmma::matrix_b, 16, 16, 16, __half, wmma::row_major> bb;
            wmma::load_matrix_sync(bb, g_W1x + k*16*128 + n0, 128);
            wmma::mma_sync(c, a[k], bb, c);
        }
        wmma::store_matrix_sync(cbuf[w], c, 16, wmma::mem_row_major);
        __syncwarp();
        #pragma unroll
        for (int j = 0; j < 8; ++j) {
            int idx = j*32 + lane, r = idx >> 4, cl = idx & 15;
            g_XpW[(size_t)b*16384 + (size_t)(m0 + r)*128 + n0 + cl] = __float2half(cbuf[w][idx]);
        }
        __syncwarp();
    }
}

// k_main: scan only (gates + v), m8n32k16 merged phase, 2 barriers/step
#define B1W  648
#define B2W  136
#define HAW  264
#define SGW  780
#define OFF_B1   0
#define OFF_B2   165888
#define OFF_HA   200704
#define OFF_GSC  204928
#define SMEM_MAIN 229888

__global__ __launch_bounds__(512, 1) void k_main(
    const float* __restrict__ b_a1)
{
    extern __shared__ char sm[];
    __half* s_b1  = (__half*)(sm + OFF_B1);   // [128][648]: gates 0..511, W1h 512..639
    __half* s_b2  = (__half*)(sm + OFF_B2);   // [128][136]: W1c 0..127
    __half* s_hA  = (__half*)(sm + OFF_HA);   // [8][264]: rows 0..3 = batches, cols h|c
    float*  s_gsc = (float*)(sm + OFF_GSC);   // [8][780]: gates 0..511, vH 512.., vC 640..

    const int tid = threadIdx.x, w = tid >> 5;
    const int b0 = blockIdx.x * 4;

    {
        const __half2* whh2 = (const __half2*)g_whhT;  // [128][256]
        const __half2* w1a2 = (const __half2*)g_W1hc;  // [256][64]
        __half2* b1 = (__half2*)s_b1;
        for (int u = tid; u < 128*324; u += 512) {
            int k = u / 324, c = u % 324;
            b1[k*324 + c] = (c < 256) ? whh2[k*256 + c] :
                            (c < 320) ? w1a2[k*64 + (c - 256)] : __float2half2_rn(0.f);
        }
        __half2* b2 = (__half2*)s_b2;
        for (int u = tid; u < 128*68; u += 512) {
            int k = u / 68, c = u % 68;
            b2[k*68 + c] = (c < 64) ? w1a2[(128 + k)*64 + c] : __float2half2_rn(0.f);
        }
        __half2* hz = (__half2*)s_hA;
        for (int u = tid; u < 8*132; u += 512) hz[u] = __float2half2_rn(0.f);
    }
    const int b4 = tid >> 7, i = tid & 127;
    const float bs0 = g_bsum[i];
    const float bs1 = g_bsum[128 + i];
    const float bs2 = g_bsum[256 + i];
    const float bs3 = g_bsum[384 + i];
    const float ba1i = b_a1[i];
    __syncthreads();

    float creg = 0.f;

    for (int t = 0; t < 64; ++t) {
        const size_t grow = ((size_t)(b0 + b4)*64 + t)*512;
        float gp0 = g_gih[grow + i];
        float gp1 = g_gih[grow + 128 + i];
        float gp2 = g_gih[grow + 256 + i];
        float gp3 = g_gih[grow + 384 + i];

        // gate tile (all 16 warps)
        {
            wmma::fragment<wmma::accumulator, 8, 32, 16, float> c0;
            wmma::fill_fragment(c0, 0.f);
            #pragma unroll
            for (int k = 0; k < 8; ++k) {
                wmma::fragment<wmma::matrix_a, 8, 32, 16, __half, wmma::row_major> a;
                wmma::fragment<wmma::matrix_b, 8, 32, 16, __half, wmma::row_major> b;
                wmma::load_matrix_sync(a, s_hA + k*16, HAW);
                wmma::load_matrix_sync(b, s_b1 + (k*16)*B1W + w*32, B1W);
                wmma::mma_sync(c0, a, b, c0);
            }
            wmma::store_matrix_sync(s_gsc + w*32, c0, SGW, wmma::mem_row_major);
        }
        // v tiles (warps 0..7)
        if (w < 4) {
            wmma::fragment<wmma::accumulator, 8, 32, 16, float> cv;
            wmma::fill_fragment(cv, 0.f);
            #pragma unroll
            for (int k = 0; k < 8; ++k) {
                wmma::fragment<wmma::matrix_a, 8, 32, 16, __half, wmma::row_major> a;
                wmma::fragment<wmma::matrix_b, 8, 32, 16, __half, wmma::row_major> b;
                wmma::load_matrix_sync(a, s_hA + k*16, HAW);
                wmma::load_matrix_sync(b, s_b1 + (k*16)*B1W + 512 + w*32, B1W);
                wmma::mma_sync(cv, a, b, cv);
            }
            wmma::store_matrix_sync(s_gsc + 512 + w*32, cv, SGW, wmma::mem_row_major);
        } else if (w < 8) {
            wmma::fragment<wmma::accumulator, 8, 32, 16, float> cv;
            wmma::fill_fragment(cv, 0.f);
            #pragma unroll
            for (int k = 0; k < 8; ++k) {
                wmma::fragment<wmma::matrix_a, 8, 32, 16, __half, wmma::row_major> a;
                wmma::fragment<wmma::matrix_b, 8, 32, 16, __half, wmma::row_major> b;
                wmma::load_matrix_sync(a, s_hA + 128 + k*16, HAW);
                wmma::load_matrix_sync(b, s_b2 + (k*16)*B2W + (w - 4)*32, B2W);
                wmma::mma_sync(cv, a, b, cv);
            }
            wmma::store_matrix_sync(s_gsc + 640 + (w - 4)*32, cv, SGW, wmma::mem_row_major);
        }
        __syncthreads();

        // epilogue: gates + v + state update, stream v to global
        {
            const float* gr = s_gsc + b4*SGW;
            float gi = gr[i]       + gp0 + bs0;
            float gf = gr[128 + i] + gp1 + bs1;
            float gg = gr[256 + i] + gp2 + bs2;
            float go = gr[384 + i] + gp3 + bs3;
            float gv = gr[512 + i] + gr[640 + i] + ba1i;
            creg = sigmoid_fast(gf)*creg + sigmoid_fast(gi)*tanh_fast(gg);
            float hn = sigmoid_fast(go) * tanh_fast(creg);
            s_hA[b4*HAW + i]       = __float2half(hn);
            s_hA[b4*HAW + 128 + i] = __float2half(creg);
            g_vh[((size_t)(b0 + b4)*64 + t)*128 + i] = __float2half(gv);
        }
        __syncthreads();
    }
}

// k_phaseB: fully parallel attention+softmax+output, one CTA per batch
#define PB_XP   0
#define PB_VT   33280
#define PB_W2   49664
#define PB_RED  50176
#define SMEM_PB 50304

__global__ __launch_bounds__(512) void k_phaseB(
    const float* __restrict__ w_a2, const float* __restrict__ b_a2p,
    float* __restrict__ out)
{
    extern __shared__ char sm[];
    __half2* s_xp = (__half2*)(sm + PB_XP);   // [128][65]
    __half2* s_vt = (__half2*)(sm + PB_VT);   // [64][64]
    float*   s_w2 = (float*)(sm + PB_W2);
    float*   s_r  = (float*)(sm + PB_RED);    // [2][16]

    const int tid = threadIdx.x;
    const int b = blockIdx.x;
    const float b_a2 = b_a2p[0];

    {
        const __half2* xr = (const __half2*)(g_XpW + (size_t)b*16384);
        for (int u = tid; u < 8192; u += 512)
            s_xp[(u >> 6)*65 + (u & 63)] = xr[u];
        const __half2* vr = (const __half2*)(g_vh + (size_t)b*8192);
        for (int u = tid; u < 4096; u += 512)
            s_vt[u] = vr[u];
        if (tid < 128) s_w2[tid] = w_a2[tid];
    }
    __syncthreads();

    const int d = tid & 127, tq = tid >> 7, w = tid >> 5, lane = tid & 31;
    const __half2* xrow = s_xp + d*65;

    for (int j = 0; j < 16; ++j) {
        int t = tq*16 + j;
        const __half2* vrow = s_vt + t*64;
        float acc0 = b_a2, acc1 = 0.f;
        #pragma unroll 16
        for (int k2 = 0; k2 < 64; k2 += 2) {
            __half2 th0 = tanh2h(__hadd2(xrow[k2], vrow[k2]));
            __half2 th1 = tanh2h(__hadd2(xrow[k2 + 1], vrow[k2 + 1]));
            float2 tf0 = __half22float2(th0);
            float2 tf1 = __half22float2(th1);
            acc0 = fmaf(tf0.x, s_w2[2*k2],     fmaf(tf0.y, s_w2[2*k2 + 1], acc0));
            acc1 = fmaf(tf1.x, s_w2[2*k2 + 2], fmaf(tf1.y, s_w2[2*k2 + 3], acc1));
        }
        float ex = __expf(acc0 + acc1);
        float ss = ex;
        #pragma unroll
        for (int o = 16; o > 0; o >>= 1) ss += __shfl_xor_sync(0xffffffffu, ss, o);
        if (lane == 0) s_r[(j & 1)*16 + w] = ss;
        __syncthreads();
        const float* rp = s_r + (j & 1)*16 + tq*4;
        float tot = rp[0] + rp[1] + rp[2] + rp[3];
        size_t oidx = ((size_t)b*64 + t)*128 + d;
        out[oidx] = (ex / tot) * g_Xa[oidx];
    }
}

extern "C" void kernel_launch(void* const* d_in, const int* in_sizes, int n_in,
                              void* d_out, int out_size)
{
    const float* X     = (const float*)d_in[0];
    const float* attri = (const float*)d_in[1];
    const float* w_at1 = (const float*)d_in[2];
    const float* b_at1 = (const float*)d_in[3];
    const float* w_at2 = (const float*)d_in[4];
    const float* b_at2 = (const float*)d_in[5];
    const float* w_a1  = (const float*)d_in[6];
    const float* b_a1  = (const float*)d_in[7];
    const float* w_a2  = (const float*)d_in[8];
    const float* b_a2  = (const float*)d_in[9];
    const float* w_ih  = (const float*)d_in[10];
    const float* w_hh  = (const float*)d_in[11];
    const float* b_ih  = (const float*)d_in[12];
    const float* b_hh  = (const float*)d_in[13];
    float* out = (float*)d_out;

    cudaFuncSetAttribute(k_main, cudaFuncAttributeMaxDynamicSharedMemorySize, SMEM_MAIN);
    cudaFuncSetAttribute(k_phaseB, cudaFuncAttributeMaxDynamicSharedMemorySize, SMEM_PB);
    k_alpha<<<1, 128>>>(attri, w_at1, b_at1, w_at2, b_at2);
    k_prep<<<(NB*NT*ND + 255)/256, 256>>>(X, w_ih, w_hh, w_a1, b_ih, b_hh);
    k_gih<<<(NB*NT)/16, 256>>>();
    k_xpw<<<NB, 256>>>();
    k_main<<<128, 512, SMEM_MAIN>>>(b_a1);
    k_phaseB<<<NB, 512, SMEM_PB>>>(w_a2, b_a2, out);
}

// round 12
// speedup vs baseline: 1.5232x; 1.0704x over previous
#include <cuda_runtime.h>
#include <cuda_fp16.h>
#include <mma.h>
using namespace nvcuda;

#define NB 512
#define NT 64
#define ND 128
#define NH 128

__device__ float  g_alpha[128];
__device__ __align__(16) float  g_Xa[NB*NT*ND];
__device__ __align__(16) __half g_Xh[NB*NT*ND];
__device__ __align__(16) __half g_wihh[512*128];
__device__ __align__(16) __half g_whhT[128*512];   // [k][g]
__device__ __align__(16) __half g_W1hc[256*128];   // [j][n]
__device__ __align__(16) __half g_W1x[64*128];
__device__ __align__(16) float  g_bsum[512];
__device__ __align__(16) __half g_gih[(size_t)NB*NT*512];   // fp16 now
__device__ __align__(16) __half g_XpW[(size_t)NB*128*128];
__device__ __align__(16) __half g_vh[(size_t)NB*NT*128];

__device__ __forceinline__ float tanh_fast(float x) {
    float y;
    asm("tanh.approx.f32 %0, %1;" : "=f"(y) : "f"(x));
    return y;
}
__device__ __forceinline__ float sigmoid_fast(float x) {
    return fmaf(0.5f, tanh_fast(0.5f * x), 0.5f);
}
__device__ __forceinline__ __half2 tanh2h(__half2 a) {
    __half2 r;
    asm("tanh.approx.f16x2 %0, %1;" : "=r"(*(unsigned*)&r) : "r"(*(unsigned*)&a));
    return r;
}

__global__ __launch_bounds__(128) void k_alpha(
    const float* __restrict__ attri, const float* __restrict__ w1,
    const float* __restrict__ b1, const float* __restrict__ w2,
    const float* __restrict__ b2)
{
    __shared__ float sv[128];
    __shared__ float sred;
    int d = threadIdx.x;
    float ar[64];
    #pragma unroll
    for (int t = 0; t < 64; ++t) ar[t] = attri[d*64 + t];
    float s = b2[0];
    for (int j = 0; j < 32; ++j) {
        float a = b1[j];
        #pragma unroll
        for (int t = 0; t < 64; ++t) a = fmaf(ar[t], w1[t*32 + j], a);
        a = (a > 0.f) ? a : 0.5f * a;
        s = fmaf(a, w2[j], s);
    }
    sv[d] = s; __syncthreads();
    if (d == 0) { float m = sv[0]; for (int i = 1; i < 128; ++i) m = fmaxf(m, sv[i]); sred = m; }
    __syncthreads();
    float ev = __expf(s - sred);
    sv[d] = ev; __syncthreads();
    if (d == 0) { float su = 0.f; for (int i = 0; i < 128; ++i) su += sv[i]; sred = su; }
    __syncthreads();
    g_alpha[d] = ev / sred;
}

__global__ __launch_bounds__(256) void k_prep(
    const float* __restrict__ X, const float* __restrict__ w_ih,
    const float* __restrict__ w_hh, const float* __restrict__ w_a1,
    const float* __restrict__ b_ih, const float* __restrict__ b_hh)
{
    int i = blockIdx.x * 256 + threadIdx.x;
    if (i < NB*NT*ND) {
        float v = X[i] * g_alpha[i & 127];
        g_Xa[i] = v;
        g_Xh[i] = __float2half(v);
    }
    if (i < 65536) {
        g_wihh[i] = __float2half(w_ih[i]);
        int g = i >> 7, k = i & 127;
        g_whhT[k*512 + g] = __float2half(w_hh[i]);
    }
    if (i < 32768) g_W1hc[i] = __float2half(w_a1[i]);
    if (i < 8192)  g_W1x[i]  = __float2half(w_a1[32768 + i]);
    if (i < 512)   g_bsum[i] = b_ih[i] + b_hh[i];
}

__global__ __launch_bounds__(256) void k_gih()
{
    __shared__ float cbuf[8][256];
    int m0 = blockIdx.x * 16;
    int w = threadIdx.x >> 5, lane = threadIdx.x & 31;
    __half2* gout = (__half2*)g_gih;
    wmma::fragment<wmma::matrix_a, 16, 16, 16, __half, wmma::row_major> a[8];
    #pragma unroll
    for (int k = 0; k < 8; ++k)
        wmma::load_matrix_sync(a[k], g_Xh + (size_t)m0*128 + k*16, 128);
    #pragma unroll
    for (int rep = 0; rep < 4; ++rep) {
        int n0 = w*16 + rep*128;
        wmma::fragment<wmma::accumulator, 16, 16, 16, float> c;
        wmma::fill_fragment(c, 0.f);
        #pragma unroll
        for (int k = 0; k < 8; ++k) {
            wmma::fragment<wmma::matrix_b, 16, 16, 16, __half, wmma::col_major> b;
            wmma::load_matrix_sync(b, g_wihh + (size_t)n0*128 + k*16, 128);
            wmma::mma_sync(c, a[k], b, c);
        }
        wmma::store_matrix_sync(cbuf[w], c, 16, wmma::mem_row_major);
        __syncwarp();
        #pragma unroll
        for (int j = 0; j < 4; ++j) {
            int u = j*32 + lane, r = u >> 3, c2 = u & 7;
            gout[(size_t)(m0 + r)*256 + (n0 >> 1) + c2] =
                __floats2half2_rn(cbuf[w][r*16 + 2*c2], cbuf[w][r*16 + 2*c2 + 1]);
        }
        __syncwarp();
    }
}

__global__ __launch_bounds__(256) void k_xpw()
{
    __shared__ float cbuf[8][256];
    int b = blockIdx.x;
    int w = threadIdx.x >> 5, lane = threadIdx.x & 31;
    const __half* Ab = g_Xh + (size_t)b * (NT*ND);
    int m0 = w * 16;
    wmma::fragment<wmma::matrix_a, 16, 16, 16, __half, wmma::col_major> a[4];
    #pragma unroll
    for (int k = 0; k < 4; ++k)
        wmma::load_matrix_sync(a[k], Ab + k*16*128 + m0, 128);
    for (int nt = 0; nt < 8; ++nt) {
        int n0 = nt * 16;
        wmma::fragment<wmma::accumulator, 16, 16, 16, float> c;
        wmma::fill_fragment(c, 0.f);
        #pragma unroll
        for (int k = 0; k < 4; ++k) {
            wmma::fragment<wmma::matrix_b, 16, 16, 16, __half, wmma::row_major> bb;
            wmma::load_matrix_sync(bb, g_W1x + k*16*128 + n0, 128);
            wmma::mma_sync(c, a[k], bb, c);
        }
        wmma::store_matrix_sync(cbuf[w], c, 16, wmma::mem_row_major);
        __syncwarp();
        #pragma unroll
        for (int j = 0; j < 8; ++j) {
            int idx = j*32 + lane, r = idx >> 4, cl = idx & 15;
            g_XpW[(size_t)b*16384 + (size_t)(m0 + r)*128 + n0 + cl] = __float2half(cbuf[w][idx]);
        }
        __syncwarp();
    }
}

// k_main: scan with gate-weight B-fragments hoisted in registers
#define B1W  648
#define B2W  136
#define HAW  264
#define SGW  780
#define OFF_B1   0
#define OFF_B2   165888
#define OFF_HA   200704
#define OFF_GSC  204928
#define SMEM_MAIN 229888

__global__ __launch_bounds__(512, 1) void k_main(
    const float* __restrict__ b_a1)
{
    extern __shared__ char sm[];
    __half* s_b1  = (__half*)(sm + OFF_B1);   // [128][648]: gates 0..511, W1h 512..639
    __half* s_b2  = (__half*)(sm + OFF_B2);   // [128][136]: W1c 0..127
    __half* s_hA  = (__half*)(sm + OFF_HA);   // [8][264]: rows 0..3 = batches, cols h|c
    float*  s_gsc = (float*)(sm + OFF_GSC);   // [8][780]: gates 0..511, vH 512.., vC 640..

    const int tid = threadIdx.x, w = tid >> 5;
    const int b0 = blockIdx.x * 4;

    {
        const __half2* whh2 = (const __half2*)g_whhT;  // [128][256]
        const __half2* w1a2 = (const __half2*)g_W1hc;  // [256][64]
        __half2* b1 = (__half2*)s_b1;
        for (int u = tid; u < 128*324; u += 512) {
            int k = u / 324, c = u % 324;
            b1[k*324 + c] = (c < 256) ? whh2[k*256 + c] :
                            (c < 320) ? w1a2[k*64 + (c - 256)] : __float2half2_rn(0.f);
        }
        __half2* b2 = (__half2*)s_b2;
        for (int u = tid; u < 128*68; u += 512) {
            int k = u / 68, c = u % 68;
            b2[k*68 + c] = (c < 64) ? w1a2[(128 + k)*64 + c] : __float2half2_rn(0.f);
        }
        __half2* hz = (__half2*)s_hA;
        for (int u = tid; u < 8*132; u += 512) hz[u] = __float2half2_rn(0.f);
    }
    const int b4 = tid >> 7, i = tid & 127;
    const float bs0 = g_bsum[i];
    const float bs1 = g_bsum[128 + i];
    const float bs2 = g_bsum[256 + i];
    const float bs3 = g_bsum[384 + i];
    const float ba1i = b_a1[i];
    __syncthreads();

    // hoist this warp's gate-tile B fragments into registers (time-invariant)
    wmma::fragment<wmma::matrix_b, 8, 32, 16, __half, wmma::row_major> bG[8];
    #pragma unroll
    for (int k = 0; k < 8; ++k)
        wmma::load_matrix_sync(bG[k], s_b1 + (k*16)*B1W + w*32, B1W);

    float creg = 0.f;

    for (int t = 0; t < 64; ++t) {
        const size_t grow = ((size_t)(b0 + b4)*64 + t)*512;
        float gp0 = __half2float(g_gih[grow + i]);
        float gp1 = __half2float(g_gih[grow + 128 + i]);
        float gp2 = __half2float(g_gih[grow + 256 + i]);
        float gp3 = __half2float(g_gih[grow + 384 + i]);

        // gate tile: B from registers
        {
            wmma::fragment<wmma::accumulator, 8, 32, 16, float> c0;
            wmma::fill_fragment(c0, 0.f);
            #pragma unroll
            for (int k = 0; k < 8; ++k) {
                wmma::fragment<wmma::matrix_a, 8, 32, 16, __half, wmma::row_major> a;
                wmma::load_matrix_sync(a, s_hA + k*16, HAW);
                wmma::mma_sync(c0, a, bG[k], c0);
            }
            wmma::store_matrix_sync(s_gsc + w*32, c0, SGW, wmma::mem_row_major);
        }
        // v tiles (warps 0..7), B streamed from smem
        if (w < 4) {
            wmma::fragment<wmma::accumulator, 8, 32, 16, float> cv;
            wmma::fill_fragment(cv, 0.f);
            #pragma unroll
            for (int k = 0; k < 8; ++k) {
                wmma::fragment<wmma::matrix_a, 8, 32, 16, __half, wmma::row_major> a;
                wmma::fragment<wmma::matrix_b, 8, 32, 16, __half, wmma::row_major> b;
                wmma::load_matrix_sync(a, s_hA + k*16, HAW);
                wmma::load_matrix_sync(b, s_b1 + (k*16)*B1W + 512 + w*32, B1W);
                wmma::mma_sync(cv, a, b, cv);
            }
            wmma::store_matrix_sync(s_gsc + 512 + w*32, cv, SGW, wmma::mem_row_major);
        } else if (w < 8) {
            wmma::fragment<wmma::accumulator, 8, 32, 16, float> cv;
            wmma::fill_fragment(cv, 0.f);
            #pragma unroll
            for (int k = 0; k < 8; ++k) {
                wmma::fragment<wmma::matrix_a, 8, 32, 16, __half, wmma::row_major> a;
                wmma::fragment<wmma::matrix_b, 8, 32, 16, __half, wmma::row_major> b;
                wmma::load_matrix_sync(a, s_hA + 128 + k*16, HAW);
                wmma::load_matrix_sync(b, s_b2 + (k*16)*B2W + (w - 4)*32, B2W);
                wmma::mma_sync(cv, a, b, cv);
            }
            wmma::store_matrix_sync(s_gsc + 640 + (w - 4)*32, cv, SGW, wmma::mem_row_major);
        }
        __syncthreads();

        // epilogue: gates + v + state update, stream v to global
        {
            const float* gr = s_gsc + b4*SGW;
            float gi = gr[i]       + gp0 + bs0;
            float gf = gr[128 + i] + gp1 + bs1;
            float gg = gr[256 + i] + gp2 + bs2;
            float go = gr[384 + i] + gp3 + bs3;
            float gv = gr[512 + i] + gr[640 + i] + ba1i;
            creg = sigmoid_fast(gf)*creg + sigmoid_fast(gi)*tanh_fast(gg);
            float hn = sigmoid_fast(go) * tanh_fast(creg);
            s_hA[b4*HAW + i]       = __float2half(hn);
            s_hA[b4*HAW + 128 + i] = __float2half(creg);
            g_vh[((size_t)(b0 + b4)*64 + t)*128 + i] = __float2half(gv);
        }
        __syncthreads();
    }
}

// k_phaseB: fully parallel attention+softmax+output, one CTA per batch
#define PB_XP   0
#define PB_VT   33280
#define PB_W2   49664
#define PB_RED  50176
#define SMEM_PB 50304

__global__ __launch_bounds__(512) void k_phaseB(
    const float* __restrict__ w_a2, const float* __restrict__ b_a2p,
    float* __restrict__ out)
{
    extern __shared__ char sm[];
    __half2* s_xp = (__half2*)(sm + PB_XP);   // [128][65]
    __half2* s_vt = (__half2*)(sm + PB_VT);   // [64][64]
    float*   s_w2 = (float*)(sm + PB_W2);
    float*   s_r  = (float*)(sm + PB_RED);    // [2][16]

    const int tid = threadIdx.x;
    const int b = blockIdx.x;
    const float b_a2 = b_a2p[0];

    {
        const __half2* xr = (const __half2*)(g_XpW + (size_t)b*16384);
        for (int u = tid; u < 8192; u += 512)
            s_xp[(u >> 6)*65 + (u & 63)] = xr[u];
        const __half2* vr = (const __half2*)(g_vh + (size_t)b*8192);
        for (int u = tid; u < 4096; u += 512)
            s_vt[u] = vr[u];
        if (tid < 128) s_w2[tid] = w_a2[tid];
    }
    __syncthreads();

    const int d = tid & 127, tq = tid >> 7, w = tid >> 5, lane = tid & 31;
    const __half2* xrow = s_xp + d*65;

    for (int j = 0; j < 16; ++j) {
        int t = tq*16 + j;
        const __half2* vrow = s_vt + t*64;
        float acc0 = b_a2, acc1 = 0.f;
        #pragma unroll 16
        for (int k2 = 0; k2 < 64; k2 += 2) {
            __half2 th0 = tanh2h(__hadd2(xrow[k2], vrow[k2]));
            __half2 th1 = tanh2h(__hadd2(xrow[k2 + 1], vrow[k2 + 1]));
            float2 tf0 = __half22float2(th0);
            float2 tf1 = __half22float2(th1);
            acc0 = fmaf(tf0.x, s_w2[2*k2],     fmaf(tf0.y, s_w2[2*k2 + 1], acc0));
            acc1 = fmaf(tf1.x, s_w2[2*k2 + 2], fmaf(tf1.y, s_w2[2*k2 + 3], acc1));
        }
        float ex = __expf(acc0 + acc1);
        float ss = ex;
        #pragma unroll
        for (int o = 16; o > 0; o >>= 1) ss += __shfl_xor_sync(0xffffffffu, ss, o);
        if (lane == 0) s_r[(j & 1)*16 + w] = ss;
        __syncthreads();
        const float* rp = s_r + (j & 1)*16 + tq*4;
        float tot = rp[0] + rp[1] + rp[2] + rp[3];
        size_t oidx = ((size_t)b*64 + t)*128 + d;
        out[oidx] = (ex / tot) * g_Xa[oidx];
    }
}

extern "C" void kernel_launch(void* const* d_in, const int* in_sizes, int n_in,
                              void* d_out, int out_size)
{
    const float* X     = (const float*)d_in[0];
    const float* attri = (const float*)d_in[1];
    const float* w_at1 = (const float*)d_in[2];
    const float* b_at1 = (const float*)d_in[3];
    const float* w_at2 = (const float*)d_in[4];
    const float* b_at2 = (const float*)d_in[5];
    const float* w_a1  = (const float*)d_in[6];
    const float* b_a1  = (const float*)d_in[7];
    const float* w_a2  = (const float*)d_in[8];
    const float* b_a2  = (const float*)d_in[9];
    const float* w_ih  = (const float*)d_in[10];
    const float* w_hh  = (const float*)d_in[11];
    const float* b_ih  = (const float*)d_in[12];
    const float* b_hh  = (const float*)d_in[13];
    float* out = (float*)d_out;

    cudaFuncSetAttribute(k_main, cudaFuncAttributeMaxDynamicSharedMemorySize, SMEM_MAIN);
    cudaFuncSetAttribute(k_phaseB, cudaFuncAttributeMaxDynamicSharedMemorySize, SMEM_PB);
    k_alpha<<<1, 128>>>(attri, w_at1, b_at1, w_at2, b_at2);
    k_prep<<<(NB*NT*ND + 255)/256, 256>>>(X, w_ih, w_hh, w_a1, b_ih, b_hh);
    k_gih<<<(NB*NT)/16, 256>>>();
    k_xpw<<<NB, 256>>>();
    k_main<<<128, 512, SMEM_MAIN>>>(b_a1);
    k_phaseB<<<NB, 512, SMEM_PB>>>(w_a2, b_a2, out);
}

// round 13
// speedup vs baseline: 1.8361x; 1.2054x over previous
#include <cuda_runtime.h>
#include <cuda_fp16.h>
#include <mma.h>
using namespace nvcuda;

#define NB 512
#define NT 64
#define ND 128
#define NH 128

__device__ float  g_alpha[128];
__device__ __align__(16) float  g_Xa[NB*NT*ND];
__device__ __align__(16) __half g_Xh[NB*NT*ND];
__device__ __align__(16) __half g_wihh[512*128];
__device__ __align__(16) __half g_whhT[128*512];   // [k][g]
__device__ __align__(16) __half g_W1hc[256*128];   // [j][n]
__device__ __align__(16) __half g_W1x[64*128];
__device__ __align__(16) float  g_bsum[512];
__device__ __align__(16) __half g_gih[(size_t)NB*NT*512];
__device__ __align__(16) __half g_XpW[(size_t)NB*128*128];
__device__ __align__(16) __half g_vh[(size_t)NB*NT*128];

__device__ __forceinline__ float tanh_fast(float x) {
    float y;
    asm("tanh.approx.f32 %0, %1;" : "=f"(y) : "f"(x));
    return y;
}
__device__ __forceinline__ float sigmoid_fast(float x) {
    return fmaf(0.5f, tanh_fast(0.5f * x), 0.5f);
}
__device__ __forceinline__ __half2 tanh2h(__half2 a) {
    __half2 r;
    asm("tanh.approx.f16x2 %0, %1;" : "=r"(*(unsigned*)&r) : "r"(*(unsigned*)&a));
    return r;
}

__global__ __launch_bounds__(128) void k_alpha(
    const float* __restrict__ attri, const float* __restrict__ w1,
    const float* __restrict__ b1, const float* __restrict__ w2,
    const float* __restrict__ b2)
{
    __shared__ float sv[128];
    __shared__ float sred;
    int d = threadIdx.x;
    float ar[64];
    #pragma unroll
    for (int t = 0; t < 64; ++t) ar[t] = attri[d*64 + t];
    float s = b2[0];
    for (int j = 0; j < 32; ++j) {
        float a = b1[j];
        #pragma unroll
        for (int t = 0; t < 64; ++t) a = fmaf(ar[t], w1[t*32 + j], a);
        a = (a > 0.f) ? a : 0.5f * a;
        s = fmaf(a, w2[j], s);
    }
    sv[d] = s; __syncthreads();
    if (d == 0) { float m = sv[0]; for (int i = 1; i < 128; ++i) m = fmaxf(m, sv[i]); sred = m; }
    __syncthreads();
    float ev = __expf(s - sred);
    sv[d] = ev; __syncthreads();
    if (d == 0) { float su = 0.f; for (int i = 0; i < 128; ++i) su += sv[i]; sred = su; }
    __syncthreads();
    g_alpha[d] = ev / sred;
}

__global__ __launch_bounds__(256) void k_prep(
    const float* __restrict__ X, const float* __restrict__ w_ih,
    const float* __restrict__ w_hh, const float* __restrict__ w_a1,
    const float* __restrict__ b_ih, const float* __restrict__ b_hh)
{
    int i = blockIdx.x * 256 + threadIdx.x;
    if (i < NB*NT*ND) {
        float v = X[i] * g_alpha[i & 127];
        g_Xa[i] = v;
        g_Xh[i] = __float2half(v);
    }
    if (i < 65536) {
        g_wihh[i] = __float2half(w_ih[i]);
        int g = i >> 7, k = i & 127;
        g_whhT[k*512 + g] = __float2half(w_hh[i]);
    }
    if (i < 32768) g_W1hc[i] = __float2half(w_a1[i]);
    if (i < 8192)  g_W1x[i]  = __float2half(w_a1[32768 + i]);
    if (i < 512)   g_bsum[i] = b_ih[i] + b_hh[i];
}

// k_gih v2: smem-staged GEMM. 256 CTAs x 128 rows.
// gih[m][g] = sum_k Xh[m][k] * w_ih[g][k]
#define GW 68   // half2 row stride for 128-half rows (pad 8 halves)
#define KG_A   0
#define KG_B   34816
#define KG_C   69632
#define SMEM_KG 77824

__global__ __launch_bounds__(256) void k_gih()
{
    extern __shared__ char sg[];
    __half* sA = (__half*)(sg + KG_A);    // [128][136]: rows m, cols k
    __half* sB = (__half*)(sg + KG_B);    // [128][136]: rows n(local), cols k
    float (*cbuf)[256] = (float(*)[256])(sg + KG_C);

    const int m0 = blockIdx.x * 128;
    const int tid = threadIdx.x, w = tid >> 5, lane = tid & 31;
    __half2* gout = (__half2*)g_gih;

    // stage A coalesced
    {
        const __half2* Ag = (const __half2*)(g_Xh + (size_t)m0*128);
        __half2* Ah = (__half2*)sA;
        for (int u = tid; u < 8192; u += 256)
            Ah[(u >> 6)*GW + (u & 63)] = Ag[u];
    }

    wmma::fragment<wmma::matrix_a, 16, 16, 16, __half, wmma::row_major> a[8];

    for (int nc = 0; nc < 4; ++nc) {
        if (nc > 0) __syncthreads();   // prior compute done before sB overwrite
        {
            const __half2* Bg = (const __half2*)(g_wihh + (size_t)nc*128*128);
            __half2* Bh = (__half2*)sB;
            for (int u = tid; u < 8192; u += 256)
                Bh[(u >> 6)*GW + (u & 63)] = Bg[u];
        }
        __syncthreads();
        if (nc == 0) {
            #pragma unroll
            for (int k = 0; k < 8; ++k)
                wmma::load_matrix_sync(a[k], sA + (w*16)*136 + k*16, 136);
        }
        #pragma unroll
        for (int nt = 0; nt < 8; ++nt) {
            wmma::fragment<wmma::accumulator, 16, 16, 16, float> c;
            wmma::fill_fragment(c, 0.f);
            #pragma unroll
            for (int k = 0; k < 8; ++k) {
                wmma::fragment<wmma::matrix_b, 16, 16, 16, __half, wmma::col_major> b;
                wmma::load_matrix_sync(b, sB + (nt*16)*136 + k*16, 136);
                wmma::mma_sync(c, a[k], b, c);
            }
            wmma::store_matrix_sync(cbuf[w], c, 16, wmma::mem_row_major);
            __syncwarp();
            int n0 = nc*128 + nt*16;
            #pragma unroll
            for (int j = 0; j < 4; ++j) {
                int u = j*32 + lane, r = u >> 3, c2 = u & 7;
                gout[(size_t)(m0 + w*16 + r)*256 + (n0 >> 1) + c2] =
                    __floats2half2_rn(cbuf[w][r*16 + 2*c2], cbuf[w][r*16 + 2*c2 + 1]);
            }
            __syncwarp();
        }
    }
}

// k_xpw v2: smem-staged. XpW[b][d][n] = sum_t Xh[b][t][d] * W1x[t][n]
__global__ __launch_bounds__(256) void k_xpw()
{
    __shared__ __half s_x[64*136];   // [t][d] padded
    __shared__ __half s_w[64*136];   // [t][n] padded
    __shared__ float cbuf[8][256];

    const int b = blockIdx.x;
    const int tid = threadIdx.x, w = tid >> 5, lane = tid & 31;

    {
        const __half2* xg = (const __half2*)(g_Xh + (size_t)b*(NT*ND));
        __half2* xh = (__half2*)s_x;
        for (int u = tid; u < 4096; u += 256)
            xh[(u >> 6)*GW + (u & 63)] = xg[u];
        const __half2* wg = (const __half2*)g_W1x;
        __half2* wh = (__half2*)s_w;
        for (int u = tid; u < 4096; u += 256)
            wh[(u >> 6)*GW + (u & 63)] = wg[u];
    }
    __syncthreads();

    const int m0 = w * 16;
    wmma::fragment<wmma::matrix_a, 16, 16, 16, __half, wmma::col_major> a[4];
    #pragma unroll
    for (int k = 0; k < 4; ++k)
        wmma::load_matrix_sync(a[k], s_x + (k*16)*136 + m0, 136);
    #pragma unroll
    for (int nt = 0; nt < 8; ++nt) {
        int n0 = nt * 16;
        wmma::fragment<wmma::accumulator, 16, 16, 16, float> c;
        wmma::fill_fragment(c, 0.f);
        #pragma unroll
        for (int k = 0; k < 4; ++k) {
            wmma::fragment<wmma::matrix_b, 16, 16, 16, __half, wmma::row_major> bb;
            wmma::load_matrix_sync(bb, s_w + (k*16)*136 + n0, 136);
            wmma::mma_sync(c, a[k], bb, c);
        }
        wmma::store_matrix_sync(cbuf[w], c, 16, wmma::mem_row_major);
        __syncwarp();
        #pragma unroll
        for (int j = 0; j < 8; ++j) {
            int idx = j*32 + lane, r = idx >> 4, cl = idx & 15;
            g_XpW[(size_t)b*16384 + (size_t)(m0 + r)*128 + n0 + cl] = __float2half(cbuf[w][idx]);
        }
        __syncwarp();
    }
}

// k_main: scan with gate-weight B-fragments hoisted in registers (unchanged)
#define B1W  648
#define B2W  136
#define HAW  264
#define SGW  780
#define OFF_B1   0
#define OFF_B2   165888
#define OFF_HA   200704
#define OFF_GSC  204928
#define SMEM_MAIN 229888

__global__ __launch_bounds__(512, 1) void k_main(
    const float* __restrict__ b_a1)
{
    extern __shared__ char sm[];
    __half* s_b1  = (__half*)(sm + OFF_B1);
    __half* s_b2  = (__half*)(sm + OFF_B2);
    __half* s_hA  = (__half*)(sm + OFF_HA);
    float*  s_gsc = (float*)(sm + OFF_GSC);

    const int tid = threadIdx.x, w = tid >> 5;
    const int b0 = blockIdx.x * 4;

    {
        const __half2* whh2 = (const __half2*)g_whhT;
        const __half2* w1a2 = (const __half2*)g_W1hc;
        __half2* b1 = (__half2*)s_b1;
        for (int u = tid; u < 128*324; u += 512) {
            int k = u / 324, c = u % 324;
            b1[k*324 + c] = (c < 256) ? whh2[k*256 + c] :
                            (c < 320) ? w1a2[k*64 + (c - 256)] : __float2half2_rn(0.f);
        }
        __half2* b2 = (__half2*)s_b2;
        for (int u = tid; u < 128*68; u += 512) {
            int k = u / 68, c = u % 68;
            b2[k*68 + c] = (c < 64) ? w1a2[(128 + k)*64 + c] : __float2half2_rn(0.f);
        }
        __half2* hz = (__half2*)s_hA;
        for (int u = tid; u < 8*132; u += 512) hz[u] = __float2half2_rn(0.f);
    }
    const int b4 = tid >> 7, i = tid & 127;
    const float bs0 = g_bsum[i];
    const float bs1 = g_bsum[128 + i];
    const float bs2 = g_bsum[256 + i];
    const float bs3 = g_bsum[384 + i];
    const float ba1i = b_a1[i];
    __syncthreads();

    wmma::fragment<wmma::matrix_b, 8, 32, 16, __half, wmma::row_major> bG[8];
    #pragma unroll
    for (int k = 0; k < 8; ++k)
        wmma::load_matrix_sync(bG[k], s_b1 + (k*16)*B1W + w*32, B1W);

    float creg = 0.f;

    for (int t = 0; t < 64; ++t) {
        const size_t grow = ((size_t)(b0 + b4)*64 + t)*512;
        float gp0 = __half2float(g_gih[grow + i]);
        float gp1 = __half2float(g_gih[grow + 128 + i]);
        float gp2 = __half2float(g_gih[grow + 256 + i]);
        float gp3 = __half2float(g_gih[grow + 384 + i]);

        {
            wmma::fragment<wmma::accumulator, 8, 32, 16, float> c0;
            wmma::fill_fragment(c0, 0.f);
            #pragma unroll
            for (int k = 0; k < 8; ++k) {
                wmma::fragment<wmma::matrix_a, 8, 32, 16, __half, wmma::row_major> a;
                wmma::load_matrix_sync(a, s_hA + k*16, HAW);
                wmma::mma_sync(c0, a, bG[k], c0);
            }
            wmma::store_matrix_sync(s_gsc + w*32, c0, SGW, wmma::mem_row_major);
        }
        if (w < 4) {
            wmma::fragment<wmma::accumulator, 8, 32, 16, float> cv;
            wmma::fill_fragment(cv, 0.f);
            #pragma unroll
            for (int k = 0; k < 8; ++k) {
                wmma::fragment<wmma::matrix_a, 8, 32, 16, __half, wmma::row_major> a;
                wmma::fragment<wmma::matrix_b, 8, 32, 16, __half, wmma::row_major> b;
                wmma::load_matrix_sync(a, s_hA + k*16, HAW);
                wmma::load_matrix_sync(b, s_b1 + (k*16)*B1W + 512 + w*32, B1W);
                wmma::mma_sync(cv, a, b, cv);
            }
            wmma::store_matrix_sync(s_gsc + 512 + w*32, cv, SGW, wmma::mem_row_major);
        } else if (w < 8) {
            wmma::fragment<wmma::accumulator, 8, 32, 16, float> cv;
            wmma::fill_fragment(cv, 0.f);
            #pragma unroll
            for (int k = 0; k < 8; ++k) {
                wmma::fragment<wmma::matrix_a, 8, 32, 16, __half, wmma::row_major> a;
                wmma::fragment<wmma::matrix_b, 8, 32, 16, __half, wmma::row_major> b;
                wmma::load_matrix_sync(a, s_hA + 128 + k*16, HAW);
                wmma::load_matrix_sync(b, s_b2 + (k*16)*B2W + (w - 4)*32, B2W);
                wmma::mma_sync(cv, a, b, cv);
            }
            wmma::store_matrix_sync(s_gsc + 640 + (w - 4)*32, cv, SGW, wmma::mem_row_major);
        }
        __syncthreads();

        {
            const float* gr = s_gsc + b4*SGW;
            float gi = gr[i]       + gp0 + bs0;
            float gf = gr[128 + i] + gp1 + bs1;
            float gg = gr[256 + i] + gp2 + bs2;
            float go = gr[384 + i] + gp3 + bs3;
            float gv = gr[512 + i] + gr[640 + i] + ba1i;
            creg = sigmoid_fast(gf)*creg + sigmoid_fast(gi)*tanh_fast(gg);
            float hn = sigmoid_fast(go) * tanh_fast(creg);
            s_hA[b4*HAW + i]       = __float2half(hn);
            s_hA[b4*HAW + 128 + i] = __float2half(creg);
            g_vh[((size_t)(b0 + b4)*64 + t)*128 + i] = __float2half(gv);
        }
        __syncthreads();
    }
}

// k_phaseB: fully parallel attention+softmax+output (unchanged)
#define PB_XP   0
#define PB_VT   33280
#define PB_W2   49664
#define PB_RED  50176
#define SMEM_PB 50304

__global__ __launch_bounds__(512) void k_phaseB(
    const float* __restrict__ w_a2, const float* __restrict__ b_a2p,
    float* __restrict__ out)
{
    extern __shared__ char sm[];
    __half2* s_xp = (__half2*)(sm + PB_XP);
    __half2* s_vt = (__half2*)(sm + PB_VT);
    float*   s_w2 = (float*)(sm + PB_W2);
    float*   s_r  = (float*)(sm + PB_RED);

    const int tid = threadIdx.x;
    const int b = blockIdx.x;
    const float b_a2 = b_a2p[0];

    {
        const __half2* xr = (const __half2*)(g_XpW + (size_t)b*16384);
        for (int u = tid; u < 8192; u += 512)
            s_xp[(u >> 6)*65 + (u & 63)] = xr[u];
        const __half2* vr = (const __half2*)(g_vh + (size_t)b*8192);
        for (int u = tid; u < 4096; u += 512)
            s_vt[u] = vr[u];
        if (tid < 128) s_w2[tid] = w_a2[tid];
    }
    __syncthreads();

    const int d = tid & 127, tq = tid >> 7, w = tid >> 5, lane = tid & 31;
    const __half2* xrow = s_xp + d*65;

    for (int j = 0; j < 16; ++j) {
        int t = tq*16 + j;
        const __half2* vrow = s_vt + t*64;
        float acc0 = b_a2, acc1 = 0.f;
        #pragma unroll 16
        for (int k2 = 0; k2 < 64; k2 += 2) {
            __half2 th0 = tanh2h(__hadd2(xrow[k2], vrow[k2]));
            __half2 th1 = tanh2h(__hadd2(xrow[k2 + 1], vrow[k2 + 1]));
            float2 tf0 = __half22float2(th0);
            float2 tf1 = __half22float2(th1);
            acc0 = fmaf(tf0.x, s_w2[2*k2],     fmaf(tf0.y, s_w2[2*k2 + 1], acc0));
            acc1 = fmaf(tf1.x, s_w2[2*k2 + 2], fmaf(tf1.y, s_w2[2*k2 + 3], acc1));
        }
        float ex = __expf(acc0 + acc1);
        float ss = ex;
        #pragma unroll
        for (int o = 16; o > 0; o >>= 1) ss += __shfl_xor_sync(0xffffffffu, ss, o);
        if (lane == 0) s_r[(j & 1)*16 + w] = ss;
        __syncthreads();
        const float* rp = s_r + (j & 1)*16 + tq*4;
        float tot = rp[0] + rp[1] + rp[2] + rp[3];
        size_t oidx = ((size_t)b*64 + t)*128 + d;
        out[oidx] = (ex / tot) * g_Xa[oidx];
    }
}

extern "C" void kernel_launch(void* const* d_in, const int* in_sizes, int n_in,
                              void* d_out, int out_size)
{
    const float* X     = (const float*)d_in[0];
    const float* attri = (const float*)d_in[1];
    const float* w_at1 = (const float*)d_in[2];
    const float* b_at1 = (const float*)d_in[3];
    const float* w_at2 = (const float*)d_in[4];
    const float* b_at2 = (const float*)d_in[5];
    const float* w_a1  = (const float*)d_in[6];
    const float* b_a1  = (const float*)d_in[7];
    const float* w_a2  = (const float*)d_in[8];
    const float* b_a2  = (const float*)d_in[9];
    const float* w_ih  = (const float*)d_in[10];
    const float* w_hh  = (const float*)d_in[11];
    const float* b_ih  = (const float*)d_in[12];
    const float* b_hh  = (const float*)d_in[13];
    float* out = (float*)d_out;

    cudaFuncSetAttribute(k_gih, cudaFuncAttributeMaxDynamicSharedMemorySize, SMEM_KG);
    cudaFuncSetAttribute(k_main, cudaFuncAttributeMaxDynamicSharedMemorySize, SMEM_MAIN);
    cudaFuncSetAttribute(k_phaseB, cudaFuncAttributeMaxDynamicSharedMemorySize, SMEM_PB);
    k_alpha<<<1, 128>>>(attri, w_at1, b_at1, w_at2, b_at2);
    k_prep<<<(NB*NT*ND + 255)/256, 256>>>(X, w_ih, w_hh, w_a1, b_ih, b_hh);
    k_gih<<<256, 256, SMEM_KG>>>();
    k_xpw<<<NB, 256>>>();
    k_main<<<128, 512, SMEM_MAIN>>>(b_a1);
    k_phaseB<<<NB, 512, SMEM_PB>>>(w_a2, b_a2, out);
}

// round 14
// speedup vs baseline: 1.9779x; 1.0772x over previous
#include <cuda_runtime.h>
#include <cuda_fp16.h>
#include <mma.h>
using namespace nvcuda;

#define NB 512
#define NT 64
#define ND 128
#define NH 128

__device__ float  g_alpha[128];
__device__ __align__(16) float  g_Xa[NB*NT*ND];
__device__ __align__(16) __half g_Xh[NB*NT*ND];
__device__ __align__(16) __half g_wihh[512*128];
__device__ __align__(16) __half g_whhT[128*512];   // [k][g]
__device__ __align__(16) __half g_W1hc[256*128];   // [j][n]
__device__ __align__(16) __half g_W1x[64*128];
__device__ __align__(16) float  g_bsum[512];
__device__ __align__(16) __half g_gih[(size_t)NB*NT*512];
__device__ __align__(16) __half g_XpW[(size_t)NB*128*128];
__device__ __align__(16) __half g_vh[(size_t)NB*NT*128];
__device__ __align__(16) __half g_hc[(size_t)NB*NT*256];   // state trajectory [b][t][h|c]

__device__ __forceinline__ float tanh_fast(float x) {
    float y;
    asm("tanh.approx.f32 %0, %1;" : "=f"(y) : "f"(x));
    return y;
}
__device__ __forceinline__ float sigmoid_fast(float x) {
    return fmaf(0.5f, tanh_fast(0.5f * x), 0.5f);
}
__device__ __forceinline__ __half2 tanh2h(__half2 a) {
    __half2 r;
    asm("tanh.approx.f16x2 %0, %1;" : "=r"(*(unsigned*)&r) : "r"(*(unsigned*)&a));
    return r;
}

__global__ __launch_bounds__(128) void k_alpha(
    const float* __restrict__ attri, const float* __restrict__ w1,
    const float* __restrict__ b1, const float* __restrict__ w2,
    const float* __restrict__ b2)
{
    __shared__ float sv[128];
    __shared__ float sred;
    int d = threadIdx.x;
    float ar[64];
    #pragma unroll
    for (int t = 0; t < 64; ++t) ar[t] = attri[d*64 + t];
    float s = b2[0];
    for (int j = 0; j < 32; ++j) {
        float a = b1[j];
        #pragma unroll
        for (int t = 0; t < 64; ++t) a = fmaf(ar[t], w1[t*32 + j], a);
        a = (a > 0.f) ? a : 0.5f * a;
        s = fmaf(a, w2[j], s);
    }
    sv[d] = s; __syncthreads();
    if (d == 0) { float m = sv[0]; for (int i = 1; i < 128; ++i) m = fmaxf(m, sv[i]); sred = m; }
    __syncthreads();
    float ev = __expf(s - sred);
    sv[d] = ev; __syncthreads();
    if (d == 0) { float su = 0.f; for (int i = 0; i < 128; ++i) su += sv[i]; sred = su; }
    __syncthreads();
    g_alpha[d] = ev / sred;
}

__global__ __launch_bounds__(256) void k_prep(
    const float* __restrict__ X, const float* __restrict__ w_ih,
    const float* __restrict__ w_hh, const float* __restrict__ w_a1,
    const float* __restrict__ b_ih, const float* __restrict__ b_hh)
{
    int i = blockIdx.x * 256 + threadIdx.x;
    if (i < NB*NT*ND) {
        float v = X[i] * g_alpha[i & 127];
        g_Xa[i] = v;
        g_Xh[i] = __float2half(v);
    }
    if (i < 131072) {   // zero t=0 state rows
        int b = i >> 8, j = i & 255;
        g_hc[(size_t)b*16384 + j] = __float2half(0.f);
    }
    if (i < 65536) {
        g_wihh[i] = __float2half(w_ih[i]);
        int g = i >> 7, k = i & 127;
        g_whhT[k*512 + g] = __float2half(w_hh[i]);
    }
    if (i < 32768) g_W1hc[i] = __float2half(w_a1[i]);
    if (i < 8192)  g_W1x[i]  = __float2half(w_a1[32768 + i]);
    if (i < 512)   g_bsum[i] = b_ih[i] + b_hh[i];
}

// k_gih: smem-staged GEMM (proven R12)
#define GW 68
#define KG_A   0
#define KG_B   34816
#define KG_C   69632
#define SMEM_KG 77824

__global__ __launch_bounds__(256) void k_gih()
{
    extern __shared__ char sg[];
    __half* sA = (__half*)(sg + KG_A);
    __half* sB = (__half*)(sg + KG_B);
    float (*cbuf)[256] = (float(*)[256])(sg + KG_C);

    const int m0 = blockIdx.x * 128;
    const int tid = threadIdx.x, w = tid >> 5, lane = tid & 31;
    __half2* gout = (__half2*)g_gih;

    {
        const __half2* Ag = (const __half2*)(g_Xh + (size_t)m0*128);
        __half2* Ah = (__half2*)sA;
        for (int u = tid; u < 8192; u += 256)
            Ah[(u >> 6)*GW + (u & 63)] = Ag[u];
    }

    wmma::fragment<wmma::matrix_a, 16, 16, 16, __half, wmma::row_major> a[8];

    for (int nc = 0; nc < 4; ++nc) {
        if (nc > 0) __syncthreads();
        {
            const __half2* Bg = (const __half2*)(g_wihh + (size_t)nc*128*128);
            __half2* Bh = (__half2*)sB;
            for (int u = tid; u < 8192; u += 256)
                Bh[(u >> 6)*GW + (u & 63)] = Bg[u];
        }
        __syncthreads();
        if (nc == 0) {
            #pragma unroll
            for (int k = 0; k < 8; ++k)
                wmma::load_matrix_sync(a[k], sA + (w*16)*136 + k*16, 136);
        }
        #pragma unroll
        for (int nt = 0; nt < 8; ++nt) {
            wmma::fragment<wmma::accumulator, 16, 16, 16, float> c;
            wmma::fill_fragment(c, 0.f);
            #pragma unroll
            for (int k = 0; k < 8; ++k) {
                wmma::fragment<wmma::matrix_b, 16, 16, 16, __half, wmma::col_major> b;
                wmma::load_matrix_sync(b, sB + (nt*16)*136 + k*16, 136);
                wmma::mma_sync(c, a[k], b, c);
            }
            wmma::store_matrix_sync(cbuf[w], c, 16, wmma::mem_row_major);
            __syncwarp();
            int n0 = nc*128 + nt*16;
            #pragma unroll
            for (int j = 0; j < 4; ++j) {
                int u = j*32 + lane, r = u >> 3, c2 = u & 7;
                gout[(size_t)(m0 + w*16 + r)*256 + (n0 >> 1) + c2] =
                    __floats2half2_rn(cbuf[w][r*16 + 2*c2], cbuf[w][r*16 + 2*c2 + 1]);
            }
            __syncwarp();
        }
    }
}

// k_xpw: smem-staged (proven R12)
__global__ __launch_bounds__(256) void k_xpw()
{
    __shared__ __half s_x[64*136];
    __shared__ __half s_w[64*136];
    __shared__ float cbuf[8][256];

    const int b = blockIdx.x;
    const int tid = threadIdx.x, w = tid >> 5, lane = tid & 31;

    {
        const __half2* xg = (const __half2*)(g_Xh + (size_t)b*(NT*ND));
        __half2* xh = (__half2*)s_x;
        for (int u = tid; u < 4096; u += 256)
            xh[(u >> 6)*GW + (u & 63)] = xg[u];
        const __half2* wg = (const __half2*)g_W1x;
        __half2* wh = (__half2*)s_w;
        for (int u = tid; u < 4096; u += 256)
            wh[(u >> 6)*GW + (u & 63)] = wg[u];
    }
    __syncthreads();

    const int m0 = w * 16;
    wmma::fragment<wmma::matrix_a, 16, 16, 16, __half, wmma::col_major> a[4];
    #pragma unroll
    for (int k = 0; k < 4; ++k)
        wmma::load_matrix_sync(a[k], s_x + (k*16)*136 + m0, 136);
    #pragma unroll
    for (int nt = 0; nt < 8; ++nt) {
        int n0 = nt * 16;
        wmma::fragment<wmma::accumulator, 16, 16, 16, float> c;
        wmma::fill_fragment(c, 0.f);
        #pragma unroll
        for (int k = 0; k < 4; ++k) {
            wmma::fragment<wmma::matrix_b, 16, 16, 16, __half, wmma::row_major> bb;
            wmma::load_matrix_sync(bb, s_w + (k*16)*136 + n0, 136);
            wmma::mma_sync(c, a[k], bb, c);
        }
        wmma::store_matrix_sync(cbuf[w], c, 16, wmma::mem_row_major);
        __syncwarp();
        #pragma unroll
        for (int j = 0; j < 8; ++j) {
            int idx = j*32 + lane, r = idx >> 4, cl = idx & 15;
            g_XpW[(size_t)b*16384 + (size_t)(m0 + r)*128 + n0 + cl] = __float2half(cbuf[w][idx]);
        }
        __syncwarp();
    }
}

// k_main: gates-only scan; bG in registers; streams (h,c) trajectory
#define B1W  520
#define HAW  264
#define SGW  516
#define OFF_B1   0
#define OFF_HA   133120
#define OFF_GSC  137344
#define SMEM_MAIN 153856

__global__ __launch_bounds__(512, 1) void k_main()
{
    extern __shared__ char sm[];
    __half* s_b1  = (__half*)(sm + OFF_B1);   // [128][520]: gate weights
    __half* s_hA  = (__half*)(sm + OFF_HA);   // [8][264]
    float*  s_gsc = (float*)(sm + OFF_GSC);   // [8][516]

    const int tid = threadIdx.x, w = tid >> 5;
    const int b0 = blockIdx.x * 4;

    {
        const __half2* whh2 = (const __half2*)g_whhT;   // [128][256] half2
        __half2* b1 = (__half2*)s_b1;
        for (int u = tid; u < 128*256; u += 512)
            b1[(u >> 8)*260 + (u & 255)] = whh2[u];
        __half2* hz = (__half2*)s_hA;
        for (int u = tid; u < 8*132; u += 512) hz[u] = __float2half2_rn(0.f);
    }
    const int b4 = tid >> 7, i = tid & 127;
    const float bs0 = g_bsum[i];
    const float bs1 = g_bsum[128 + i];
    const float bs2 = g_bsum[256 + i];
    const float bs3 = g_bsum[384 + i];
    __syncthreads();

    wmma::fragment<wmma::matrix_b, 8, 32, 16, __half, wmma::row_major> bG[8];
    #pragma unroll
    for (int k = 0; k < 8; ++k)
        wmma::load_matrix_sync(bG[k], s_b1 + (k*16)*B1W + w*32, B1W);

    float creg = 0.f;

    for (int t = 0; t < 64; ++t) {
        const size_t grow = ((size_t)(b0 + b4)*64 + t)*512;
        float gp0 = __half2float(g_gih[grow + i]);
        float gp1 = __half2float(g_gih[grow + 128 + i]);
        float gp2 = __half2float(g_gih[grow + 256 + i]);
        float gp3 = __half2float(g_gih[grow + 384 + i]);

        {
            wmma::fragment<wmma::accumulator, 8, 32, 16, float> c0;
            wmma::fill_fragment(c0, 0.f);
            #pragma unroll
            for (int k = 0; k < 8; ++k) {
                wmma::fragment<wmma::matrix_a, 8, 32, 16, __half, wmma::row_major> a;
                wmma::load_matrix_sync(a, s_hA + k*16, HAW);
                wmma::mma_sync(c0, a, bG[k], c0);
            }
            wmma::store_matrix_sync(s_gsc + w*32, c0, SGW, wmma::mem_row_major);
        }
        __syncthreads();

        {
            const float* gr = s_gsc + b4*SGW;
            float gi = gr[i]       + gp0 + bs0;
            float gf = gr[128 + i] + gp1 + bs1;
            float gg = gr[256 + i] + gp2 + bs2;
            float go = gr[384 + i] + gp3 + bs3;
            creg = sigmoid_fast(gf)*creg + sigmoid_fast(gi)*tanh_fast(gg);
            float hn = sigmoid_fast(go) * tanh_fast(creg);
            __half hh = __float2half(hn);
            __half hc = __float2half(creg);
            s_hA[b4*HAW + i]       = hh;
            s_hA[b4*HAW + 128 + i] = hc;
            if (t < 63) {
                size_t hb = ((size_t)(b0 + b4)*64 + t + 1)*256;
                g_hc[hb + i]       = hh;
                g_hc[hb + 128 + i] = hc;
            }
        }
        __syncthreads();
    }
}

// k_vg: v[b][t][n] = hc[b][t][:] @ W1hc + ba1, fully parallel GEMM
#define VG_A 0
#define VG_B 67584
#define VG_C 137216
#define SMEM_VG 145408

__global__ __launch_bounds__(256) void k_vg(const float* __restrict__ b_a1)
{
    extern __shared__ char sg[];
    __half* sA = (__half*)(sg + VG_A);    // [128][264]
    __half* sB = (__half*)(sg + VG_B);    // [256][136]
    float (*cbuf)[256] = (float(*)[256])(sg + VG_C);

    const int m0 = blockIdx.x * 128;
    const int tid = threadIdx.x, w = tid >> 5, lane = tid & 31;

    {
        const __half2* Ag = (const __half2*)(g_hc + (size_t)m0*256);
        __half2* Ah = (__half2*)sA;
        for (int u = tid; u < 16384; u += 256)
            Ah[(u >> 7)*132 + (u & 127)] = Ag[u];
        const __half2* Bg = (const __half2*)g_W1hc;
        __half2* Bh = (__half2*)sB;
        for (int u = tid; u < 16384; u += 256)
            Bh[(u >> 6)*GW + (u & 63)] = Bg[u];
    }
    __syncthreads();

    wmma::fragment<wmma::accumulator, 16, 16, 16, float> c[8];
    #pragma unroll
    for (int nt = 0; nt < 8; ++nt) wmma::fill_fragment(c[nt], 0.f);
    for (int k = 0; k < 16; ++k) {
        wmma::fragment<wmma::matrix_a, 16, 16, 16, __half, wmma::row_major> a;
        wmma::load_matrix_sync(a, sA + (w*16)*264 + k*16, 264);
        #pragma unroll
        for (int nt = 0; nt < 8; ++nt) {
            wmma::fragment<wmma::matrix_b, 16, 16, 16, __half, wmma::row_major> b;
            wmma::load_matrix_sync(b, sB + (k*16)*136 + nt*16, 136);
            wmma::mma_sync(c[nt], a, b, c[nt]);
        }
    }
    #pragma unroll
    for (int nt = 0; nt < 8; ++nt) {
        wmma::store_matrix_sync(cbuf[w], c[nt], 16, wmma::mem_row_major);
        __syncwarp();
        #pragma unroll
        for (int j = 0; j < 8; ++j) {
            int idx = j*32 + lane, r = idx >> 4, cl = idx & 15;
            float val = cbuf[w][idx] + __ldg(&b_a1[nt*16 + cl]);
            g_vh[(size_t)(m0 + w*16 + r)*128 + nt*16 + cl] = __float2half(val);
        }
        __syncwarp();
    }
}

// k_phaseB: unchanged (proven R10-12)
#define PB_XP   0
#define PB_VT   33280
#define PB_W2   49664
#define PB_RED  50176
#define SMEM_PB 50304

__global__ __launch_bounds__(512) void k_phaseB(
    const float* __restrict__ w_a2, const float* __restrict__ b_a2p,
    float* __restrict__ out)
{
    extern __shared__ char sm[];
    __half2* s_xp = (__half2*)(sm + PB_XP);
    __half2* s_vt = (__half2*)(sm + PB_VT);
    float*   s_w2 = (float*)(sm + PB_W2);
    float*   s_r  = (float*)(sm + PB_RED);

    const int tid = threadIdx.x;
    const int b = blockIdx.x;
    const float b_a2 = b_a2p[0];

    {
        const __half2* xr = (const __half2*)(g_XpW + (size_t)b*16384);
        for (int u = tid; u < 8192; u += 512)
            s_xp[(u >> 6)*65 + (u & 63)] = xr[u];
        const __half2* vr = (const __half2*)(g_vh + (size_t)b*8192);
        for (int u = tid; u < 4096; u += 512)
            s_vt[u] = vr[u];
        if (tid < 128) s_w2[tid] = w_a2[tid];
    }
    __syncthreads();

    const int d = tid & 127, tq = tid >> 7, w = tid >> 5, lane = tid & 31;
    const __half2* xrow = s_xp + d*65;

    for (int j = 0; j < 16; ++j) {
        int t = tq*16 + j;
        const __half2* vrow = s_vt + t*64;
        float acc0 = b_a2, acc1 = 0.f;
        #pragma unroll 16
        for (int k2 = 0; k2 < 64; k2 += 2) {
            __half2 th0 = tanh2h(__hadd2(xrow[k2], vrow[k2]));
            __half2 th1 = tanh2h(__hadd2(xrow[k2 + 1], vrow[k2 + 1]));
            float2 tf0 = __half22float2(th0);
            float2 tf1 = __half22float2(th1);
            acc0 = fmaf(tf0.x, s_w2[2*k2],     fmaf(tf0.y, s_w2[2*k2 + 1], acc0));
            acc1 = fmaf(tf1.x, s_w2[2*k2 + 2], fmaf(tf1.y, s_w2[2*k2 + 3], acc1));
        }
        float ex = __expf(acc0 + acc1);
        float ss = ex;
        #pragma unroll
        for (int o = 16; o > 0; o >>= 1) ss += __shfl_xor_sync(0xffffffffu, ss, o);
        if (lane == 0) s_r[(j & 1)*16 + w] = ss;
        __syncthreads();
        const float* rp = s_r + (j & 1)*16 + tq*4;
        float tot = rp[0] + rp[1] + rp[2] + rp[3];
        size_t oidx = ((size_t)b*64 + t)*128 + d;
        out[oidx] = (ex / tot) * g_Xa[oidx];
    }
}

extern "C" void kernel_launch(void* const* d_in, const int* in_sizes, int n_in,
                              void* d_out, int out_size)
{
    const float* X     = (const float*)d_in[0];
    const float* attri = (const float*)d_in[1];
    const float* w_at1 = (const float*)d_in[2];
    const float* b_at1 = (const float*)d_in[3];
    const float* w_at2 = (const float*)d_in[4];
    const float* b_at2 = (const float*)d_in[5];
    const float* w_a1  = (const float*)d_in[6];
    const float* b_a1  = (const float*)d_in[7];
    const float* w_a2  = (const float*)d_in[8];
    const float* b_a2  = (const float*)d_in[9];
    const float* w_ih  = (const float*)d_in[10];
    const float* w_hh  = (const float*)d_in[11];
    const float* b_ih  = (const float*)d_in[12];
    const float* b_hh  = (const float*)d_in[13];
    float* out = (float*)d_out;

    cudaFuncSetAttribute(k_gih, cudaFuncAttributeMaxDynamicSharedMemorySize, SMEM_KG);
    cudaFuncSetAttribute(k_main, cudaFuncAttributeMaxDynamicSharedMemorySize, SMEM_MAIN);
    cudaFuncSetAttribute(k_vg, cudaFuncAttributeMaxDynamicSharedMemorySize, SMEM_VG);
    cudaFuncSetAttribute(k_phaseB, cudaFuncAttributeMaxDynamicSharedMemorySize, SMEM_PB);
    k_alpha<<<1, 128>>>(attri, w_at1, b_at1, w_at2, b_at2);
    k_prep<<<(NB*NT*ND + 255)/256, 256>>>(X, w_ih, w_hh, w_a1, b_ih, b_hh);
    k_gih<<<256, 256, SMEM_KG>>>();
    k_xpw<<<NB, 256>>>();
    k_main<<<128, 512, SMEM_MAIN>>>();
    k_vg<<<256, 256, SMEM_VG>>>(b_a1);
    k_phaseB<<<NB, 512, SMEM_PB>>>(w_a2, b_a2, out);
}